// round 3
// baseline (speedup 1.0000x reference)
#include <cuda_runtime.h>
#include <math.h>

#define N_NODES 100000
#define N_EDGES 20000
#define NNZ_CNT 1600000

// ---------------- static device scratch (no allocations allowed) ----------------
__device__ int   d_hist_e[N_EDGES];
__device__ int   d_hist_n[N_NODES];
__device__ int   d_off_e[N_EDGES + 1];
__device__ int   d_off_n[N_NODES + 1];
__device__ int   d_cur_e[N_EDGES];
__device__ int   d_cur_n[N_NODES];
__device__ int   d_nbe[NNZ_CNT];          // node ids grouped by edge (edge-CSR payload)
__device__ int   d_ebn[NNZ_CNT];          // edge ids grouped by node (node-CSR payload)
__device__ float d_Binv[N_EDGES];
__device__ float d_Dinv[N_NODES];
__device__ float d_ebuf[(size_t)N_EDGES * 300];   // edge aggregate, width = F_in (<=300)
__device__ float d_gbuf[(size_t)N_EDGES * 256];   // edge GEMM output, width = F_out
__device__ float d_hbuf[(size_t)N_NODES * 256];   // node features (reused each layer)
__device__ float d_logits[N_NODES];
__device__ float d_pmax[256];
__device__ float d_acc[132];              // [0]=sumexp, [1..128]=weighted sums, [131]=gmax

// ---------------- setup kernels ----------------
__global__ void zero_kernel() {
    int stride = gridDim.x * blockDim.x;
    int i0 = blockIdx.x * blockDim.x + threadIdx.x;
    for (int i = i0; i < N_NODES; i += stride) { d_hist_n[i] = 0; d_cur_n[i] = 0; }
    for (int i = i0; i < N_EDGES; i += stride) { d_hist_e[i] = 0; d_cur_e[i] = 0; }
    if (i0 < 132) d_acc[i0] = 0.0f;
}

__global__ void hist_kernel(const int* __restrict__ ni, const int* __restrict__ ei) {
    int i = blockIdx.x * blockDim.x + threadIdx.x;
    if (i < NNZ_CNT) {
        atomicAdd(&d_hist_n[ni[i]], 1);
        atomicAdd(&d_hist_e[ei[i]], 1);
    }
}

// single-block exclusive scan (1024 threads), sequential over tiles
__device__ __forceinline__ void scan_excl_dev(const int* hist, int* off, int n) {
    __shared__ int warp_sums[32];
    __shared__ int s_carry;
    int tid = threadIdx.x;
    int lane = tid & 31, warp = tid >> 5;
    if (tid == 0) s_carry = 0;
    __syncthreads();
    for (int base = 0; base < n; base += 1024) {
        int i = base + tid;
        int v = (i < n) ? hist[i] : 0;
        int x = v;
        #pragma unroll
        for (int o = 1; o < 32; o <<= 1) {
            int y = __shfl_up_sync(0xffffffffu, x, o);
            if (lane >= o) x += y;
        }
        if (lane == 31) warp_sums[warp] = x;
        __syncthreads();
        if (warp == 0) {
            int w = warp_sums[lane];
            #pragma unroll
            for (int o = 1; o < 32; o <<= 1) {
                int y = __shfl_up_sync(0xffffffffu, w, o);
                if (lane >= o) w += y;
            }
            warp_sums[lane] = w;
        }
        __syncthreads();
        int woff = (warp > 0) ? warp_sums[warp - 1] : 0;
        int incl = x + woff;
        int carry = s_carry;
        if (i < n) off[i] = carry + incl - v;
        __syncthreads();
        if (tid == 1023) s_carry = carry + incl;
        __syncthreads();
    }
    if (tid == 0) off[n] = s_carry;
}

__global__ void scan_e_kernel() { scan_excl_dev(d_hist_e, d_off_e, N_EDGES); }
__global__ void scan_n_kernel() { scan_excl_dev(d_hist_n, d_off_n, N_NODES); }

__global__ void inv_kernel() {
    int i = blockIdx.x * blockDim.x + threadIdx.x;
    if (i < N_NODES) { int d = d_hist_n[i]; d_Dinv[i] = d > 0 ? 1.0f / (float)d : 0.0f; }
    if (i < N_EDGES) { int d = d_hist_e[i]; d_Binv[i] = d > 0 ? 1.0f / (float)d : 0.0f; }
}

__global__ void scatter_kernel(const int* __restrict__ ni, const int* __restrict__ ei) {
    int i = blockIdx.x * blockDim.x + threadIdx.x;
    if (i >= NNZ_CNT) return;
    int n = ni[i], e = ei[i];
    int pe = atomicAdd(&d_cur_e[e], 1);
    d_nbe[d_off_e[e] + pe] = n;
    int pn = atomicAdd(&d_cur_n[n], 1);
    d_ebn[d_off_n[n] + pn] = e;
}

// ---------------- node -> edge aggregation: e = Binv * (H^T src), src [N,F] ----------------
template <int F, bool FROM_ARG>
__global__ void agg_n2e_kernel(const float* __restrict__ src) {
    constexpr int NT = 256;
    constexpr int PER = (F + NT - 1) / NT;
    int e = blockIdx.x;
    int start = d_off_e[e], end = d_off_e[e + 1];
    float acc[PER];
    #pragma unroll
    for (int j = 0; j < PER; j++) acc[j] = 0.0f;
    const float* base_ptr = FROM_ARG ? src : (const float*)d_hbuf;
    for (int k = start; k < end; k++) {
        int n = __ldg(&d_nbe[k]);
        const float* row = base_ptr + (size_t)n * F;
        #pragma unroll
        for (int j = 0; j < PER; j++) {
            int f = threadIdx.x + j * NT;
            if ((F % NT == 0) || f < F) acc[j] += __ldg(&row[f]);
        }
    }
    float binv = d_Binv[e];
    float* out = d_ebuf + (size_t)e * F;
    #pragma unroll
    for (int j = 0; j < PER; j++) {
        int f = threadIdx.x + j * NT;
        if ((F % NT == 0) || f < F) out[f] = acc[j] * binv;
    }
}

// ---------------- SGEMM: d_gbuf[M,N] = d_ebuf[M,K] @ B[K,N] (fp32) ----------------
__global__ __launch_bounds__(256) void sgemm_kernel(const float* __restrict__ B,
                                                    int M, int K, int N) {
    __shared__ float As[16][65];
    __shared__ float Bs[16][64];
    const float* A = d_ebuf;
    float* C = d_gbuf;
    int tid = threadIdx.x;
    int tx = tid & 15, ty = tid >> 4;
    int row0 = blockIdx.y * 64, col0 = blockIdx.x * 64;
    float acc[4][4];
    #pragma unroll
    for (int i = 0; i < 4; i++)
        #pragma unroll
        for (int j = 0; j < 4; j++) acc[i][j] = 0.0f;

    for (int k0 = 0; k0 < K; k0 += 16) {
        #pragma unroll
        for (int i = 0; i < 4; i++) {
            int idx = tid + i * 256;
            int m = idx >> 4, kk = idx & 15;
            int gr = row0 + m, gk = k0 + kk;
            As[kk][m] = (gr < M && gk < K) ? A[(size_t)gr * K + gk] : 0.0f;
        }
        #pragma unroll
        for (int i = 0; i < 4; i++) {
            int idx = tid + i * 256;
            int kk = idx >> 6, nn = idx & 63;
            int gk = k0 + kk, gn = col0 + nn;
            Bs[kk][nn] = (gk < K && gn < N) ? B[(size_t)gk * N + gn] : 0.0f;
        }
        __syncthreads();
        #pragma unroll
        for (int kk = 0; kk < 16; kk++) {
            float a[4], b[4];
            #pragma unroll
            for (int i = 0; i < 4; i++) a[i] = As[kk][ty * 4 + i];
            #pragma unroll
            for (int j = 0; j < 4; j++) b[j] = Bs[kk][tx * 4 + j];
            #pragma unroll
            for (int i = 0; i < 4; i++)
                #pragma unroll
                for (int j = 0; j < 4; j++) acc[i][j] += a[i] * b[j];
        }
        __syncthreads();
    }
    #pragma unroll
    for (int i = 0; i < 4; i++) {
        int gr = row0 + ty * 4 + i;
        if (gr < M) {
            #pragma unroll
            for (int j = 0; j < 4; j++) {
                int gn = col0 + tx * 4 + j;
                if (gn < N) C[(size_t)gr * N + gn] = acc[i][j];
            }
        }
    }
}

// ---------------- edge -> node: h = act(Dinv * (H g) + b); optional attn logits ----------------
template <int F, bool LRELU, bool LOGITS>
__global__ void agg_e2n_kernel(const float* __restrict__ bias,
                               const float* __restrict__ attn_w,
                               const float* __restrict__ attn_b) {
    int n = blockIdx.x;
    int f = threadIdx.x;  // blockDim.x == F
    int start = d_off_n[n], end = d_off_n[n + 1];
    float acc = 0.0f;
    for (int k = start; k < end; k++) {
        int e = __ldg(&d_ebn[k]);
        acc += __ldg(&d_gbuf[(size_t)e * F + f]);
    }
    float v = acc * d_Dinv[n] + __ldg(&bias[f]);
    if (LRELU) v = (v > 0.0f) ? v : 0.01f * v;
    d_hbuf[(size_t)n * F + f] = v;
    if (LOGITS) {
        float t = v * __ldg(&attn_w[f]);
        #pragma unroll
        for (int o = 16; o > 0; o >>= 1) t += __shfl_down_sync(0xffffffffu, t, o);
        __shared__ float ws[8];
        int lane = f & 31, warp = f >> 5;
        if (lane == 0) ws[warp] = t;
        __syncthreads();
        if (f == 0) {
            float s = 0.0f;
            #pragma unroll
            for (int w = 0; w < (F >> 5); w++) s += ws[w];
            d_logits[n] = s + __ldg(&attn_b[0]);
        }
    }
}

// ---------------- attention pooling ----------------
__global__ void max1_kernel() {
    float m = -3.4e38f;
    int stride = gridDim.x * blockDim.x;
    for (int i = blockIdx.x * blockDim.x + threadIdx.x; i < N_NODES; i += stride)
        m = fmaxf(m, d_logits[i]);
    #pragma unroll
    for (int o = 16; o > 0; o >>= 1) m = fmaxf(m, __shfl_down_sync(0xffffffffu, m, o));
    __shared__ float ws[8];
    int lane = threadIdx.x & 31, warp = threadIdx.x >> 5;
    if (lane == 0) ws[warp] = m;
    __syncthreads();
    if (threadIdx.x == 0) {
        float mm = ws[0];
        for (int w = 1; w < (int)(blockDim.x >> 5); w++) mm = fmaxf(mm, ws[w]);
        d_pmax[blockIdx.x] = mm;
    }
}

__global__ void max2_kernel() {
    float m = d_pmax[threadIdx.x];  // 256 threads, 256 partials
    #pragma unroll
    for (int o = 16; o > 0; o >>= 1) m = fmaxf(m, __shfl_down_sync(0xffffffffu, m, o));
    __shared__ float ws[8];
    int lane = threadIdx.x & 31, warp = threadIdx.x >> 5;
    if (lane == 0) ws[warp] = m;
    __syncthreads();
    if (threadIdx.x == 0) {
        float mm = ws[0];
        for (int w = 1; w < 8; w++) mm = fmaxf(mm, ws[w]);
        d_acc[131] = mm;
    }
}

__global__ void pool_kernel() {
    int f = threadIdx.x;      // 128 threads
    int lane = f & 31;
    float gm = d_acc[131];
    float accf = 0.0f, accse = 0.0f;
    for (int n = blockIdx.x; n < N_NODES; n += gridDim.x) {
        float w;
        if (lane == 0) w = __expf(d_logits[n] - gm);
        w = __shfl_sync(0xffffffffu, w, 0);
        accf += w * d_hbuf[(size_t)n * 128 + f];
        if (f == 0) accse += w;
    }
    atomicAdd(&d_acc[1 + f], accf);
    if (f == 0) atomicAdd(&d_acc[0], accse);
}

__global__ void final_kernel(float* __restrict__ out) {
    int f = threadIdx.x;
    if (f < 128) out[f] = d_acc[1 + f] / d_acc[0];
}

// ---------------- launch ----------------
extern "C" void kernel_launch(void* const* d_in, const int* in_sizes, int n_in,
                              void* d_out, int out_size) {
    const float* x      = (const float*)d_in[0];
    const int*   hei    = (const int*)d_in[1];   // [2, NNZ]: row0=node_idx, row1=edge_idx
    const float* W1     = (const float*)d_in[2];
    const float* b1     = (const float*)d_in[3];
    const float* W2     = (const float*)d_in[4];
    const float* b2     = (const float*)d_in[5];
    const float* W3     = (const float*)d_in[6];
    const float* b3     = (const float*)d_in[7];
    const float* attn_w = (const float*)d_in[8];
    const float* attn_b = (const float*)d_in[9];
    const int* node_idx = hei;
    const int* edge_idx = hei + NNZ_CNT;
    float* out = (float*)d_out;

    // CSR build (amortized over 3 layers)
    zero_kernel<<<512, 256>>>();
    hist_kernel<<<(NNZ_CNT + 255) / 256, 256>>>(node_idx, edge_idx);
    scan_e_kernel<<<1, 1024>>>();
    scan_n_kernel<<<1, 1024>>>();
    inv_kernel<<<(N_NODES + 255) / 256, 256>>>();
    scatter_kernel<<<(NNZ_CNT + 255) / 256, 256>>>(node_idx, edge_idx);

    // layer 1: e = Binv*(H^T x)[E,300]; g = e@W1[E,256]; h = lrelu(Dinv*(H g)+b1)
    agg_n2e_kernel<300, true><<<N_EDGES, 256>>>(x);
    { dim3 g(4, (N_EDGES + 63) / 64); sgemm_kernel<<<g, 256>>>(W1, N_EDGES, 300, 256); }
    agg_e2n_kernel<256, true, false><<<N_NODES, 256>>>(b1, nullptr, nullptr);

    // layer 2
    agg_n2e_kernel<256, false><<<N_EDGES, 256>>>(nullptr);
    { dim3 g(4, (N_EDGES + 63) / 64); sgemm_kernel<<<g, 256>>>(W2, N_EDGES, 256, 256); }
    agg_e2n_kernel<256, true, false><<<N_NODES, 256>>>(b2, nullptr, nullptr);

    // layer 3 (no activation; fused attention logits)
    agg_n2e_kernel<256, false><<<N_EDGES, 256>>>(nullptr);
    { dim3 g(2, (N_EDGES + 63) / 64); sgemm_kernel<<<g, 256>>>(W3, N_EDGES, 256, 128); }
    agg_e2n_kernel<128, false, true><<<N_NODES, 128>>>(b3, attn_w, attn_b);

    // softmax-weighted pooling over nodes
    max1_kernel<<<256, 256>>>();
    max2_kernel<<<1, 256>>>();
    pool_kernel<<<1024, 128>>>();
    final_kernel<<<1, 128>>>(out);
}

// round 6
// speedup vs baseline: 1.6983x; 1.6983x over previous
#include <cuda_runtime.h>
#include <math.h>

#define N_NODES 100000
#define N_EDGES 20000
#define NNZ_CNT 1600000

// ---------------- static device scratch (no allocations allowed) ----------------
__device__ int   d_hist_e[N_EDGES];
__device__ int   d_hist_n[N_NODES];
__device__ int   d_off_e[N_EDGES + 1];
__device__ int   d_off_n[N_NODES + 1];
__device__ int   d_cur_e[N_EDGES];
__device__ int   d_cur_n[N_NODES];
__device__ int   d_nbe[NNZ_CNT];          // node ids grouped by edge
__device__ int   d_ebn[NNZ_CNT];          // edge ids grouped by node
__device__ float d_Binv[N_EDGES];
__device__ float d_Dinv[N_NODES];
__device__ int   d_bsum_e[8];
__device__ int   d_bsum_n[32];
__device__ __align__(16) float d_ebuf[(size_t)N_EDGES * 300];
__device__ __align__(16) float d_gbuf[(size_t)N_EDGES * 256];
__device__ __align__(16) float d_hbuf[(size_t)N_NODES * 256];
__device__ float d_logits[N_NODES];
__device__ float d_pmax[256];
__device__ float d_acc[132];              // [0]=sumexp, [1..128]=sums, [131]=gmax

// ---------------- setup ----------------
__global__ void zero_kernel() {
    int stride = gridDim.x * blockDim.x;
    int i0 = blockIdx.x * blockDim.x + threadIdx.x;
    for (int i = i0; i < N_NODES; i += stride) { d_hist_n[i] = 0; d_cur_n[i] = 0; }
    for (int i = i0; i < N_EDGES; i += stride) { d_hist_e[i] = 0; d_cur_e[i] = 0; }
    if (i0 < 132) d_acc[i0] = 0.0f;
}

__global__ void hist_kernel(const int* __restrict__ ni, const int* __restrict__ ei) {
    int i = blockIdx.x * blockDim.x + threadIdx.x;
    if (i < NNZ_CNT) {
        atomicAdd(&d_hist_n[ni[i]], 1);
        atomicAdd(&d_hist_e[ei[i]], 1);
    }
}

// ---- multi-block exclusive scan: partial sums -> scan partials -> local scan ----
#define SCAN_CHUNK 4096   // 256 threads * 16 elements

__device__ __forceinline__ void partial_sum_dev(const int* __restrict__ hist,
                                                int* __restrict__ bsum, int n) {
    int t = threadIdx.x;
    int i0 = blockIdx.x * SCAN_CHUNK + t * 16;
    int s = 0;
    #pragma unroll
    for (int j = 0; j < 16; j++) { int i = i0 + j; s += (i < n) ? hist[i] : 0; }
    #pragma unroll
    for (int o = 16; o > 0; o >>= 1) s += __shfl_down_sync(0xffffffffu, s, o);
    __shared__ int ws[8];
    int lane = t & 31, w = t >> 5;
    if (lane == 0) ws[w] = s;
    __syncthreads();
    if (t == 0) {
        int tot = 0;
        #pragma unroll
        for (int k = 0; k < 8; k++) tot += ws[k];
        bsum[blockIdx.x] = tot;
    }
}

__device__ __forceinline__ void scan_partials_dev(int* __restrict__ bsum, int nb,
                                                  int* __restrict__ off, int n) {
    int t = threadIdx.x;  // 32 threads
    int v = (t < nb) ? bsum[t] : 0;
    int x = v;
    #pragma unroll
    for (int o = 1; o < 32; o <<= 1) {
        int y = __shfl_up_sync(0xffffffffu, x, o);
        if (t >= o) x += y;
    }
    if (t < nb) bsum[t] = x - v;  // exclusive
    if (t == 31) off[n] = x;     // total
}

__device__ __forceinline__ void local_scan_dev(const int* __restrict__ hist,
                                               int* __restrict__ off,
                                               const int* __restrict__ bsum, int n) {
    int t = threadIdx.x;
    int i0 = blockIdx.x * SCAN_CHUNK + t * 16;
    int pre[16];
    int s = 0;
    #pragma unroll
    for (int j = 0; j < 16; j++) {
        int i = i0 + j;
        pre[j] = s;
        s += (i < n) ? hist[i] : 0;
    }
    int x = s;
    int lane = t & 31, w = t >> 5;
    #pragma unroll
    for (int o = 1; o < 32; o <<= 1) {
        int y = __shfl_up_sync(0xffffffffu, x, o);
        if (lane >= o) x += y;
    }
    __shared__ int ws[8];
    if (lane == 31) ws[w] = x;
    __syncthreads();
    int wbase = 0;
    #pragma unroll
    for (int k = 0; k < 8; k++) if (k < w) wbase += ws[k];
    int base = bsum[blockIdx.x] + wbase + (x - s);
    #pragma unroll
    for (int j = 0; j < 16; j++) {
        int i = i0 + j;
        if (i < n) off[i] = base + pre[j];
    }
}

// per-target wrappers (device symbols referenced directly; no symbol-address API)
__global__ void partial_sum_e_kernel() { partial_sum_dev(d_hist_e, d_bsum_e, N_EDGES); }
__global__ void partial_sum_n_kernel() { partial_sum_dev(d_hist_n, d_bsum_n, N_NODES); }
__global__ void scan_partials_e_kernel(int nb) { scan_partials_dev(d_bsum_e, nb, d_off_e, N_EDGES); }
__global__ void scan_partials_n_kernel(int nb) { scan_partials_dev(d_bsum_n, nb, d_off_n, N_NODES); }
__global__ void local_scan_e_kernel() { local_scan_dev(d_hist_e, d_off_e, d_bsum_e, N_EDGES); }
__global__ void local_scan_n_kernel() { local_scan_dev(d_hist_n, d_off_n, d_bsum_n, N_NODES); }

__global__ void inv_kernel() {
    int i = blockIdx.x * blockDim.x + threadIdx.x;
    if (i < N_NODES) { int d = d_hist_n[i]; d_Dinv[i] = d > 0 ? 1.0f / (float)d : 0.0f; }
    if (i < N_EDGES) { int d = d_hist_e[i]; d_Binv[i] = d > 0 ? 1.0f / (float)d : 0.0f; }
}

__global__ void scatter_kernel(const int* __restrict__ ni, const int* __restrict__ ei) {
    int i = blockIdx.x * blockDim.x + threadIdx.x;
    if (i >= NNZ_CNT) return;
    int n = ni[i], e = ei[i];
    int pe = atomicAdd(&d_cur_e[e], 1);
    d_nbe[d_off_e[e] + pe] = n;
    int pn = atomicAdd(&d_cur_n[n], 1);
    d_ebn[d_off_n[n] + pn] = e;
}

// ---------------- float4 helpers ----------------
__device__ __forceinline__ float4 f4add(float4 a, float4 b) {
    return make_float4(a.x + b.x, a.y + b.y, a.z + b.z, a.w + b.w);
}

// ---------------- node -> edge, F=300 (layer 1, from x) ----------------
// 128-thread group per edge (75 active float4 lanes), 2 edges per block.
__global__ __launch_bounds__(256) void agg_n2e_300(const float* __restrict__ src) {
    int grp = threadIdx.x >> 7;          // 0..1
    int lane = threadIdx.x & 127;        // 0..127
    int e = blockIdx.x * 2 + grp;
    bool act = lane < 75;
    int start = d_off_e[e], end = d_off_e[e + 1];
    const float4* base = (const float4*)src;   // row stride 75 float4
    float4 acc = make_float4(0.f, 0.f, 0.f, 0.f);
    int k = start;
    for (; k + 8 <= end; k += 8) {
        int n0 = d_nbe[k],     n1 = d_nbe[k + 1], n2 = d_nbe[k + 2], n3 = d_nbe[k + 3];
        int n4 = d_nbe[k + 4], n5 = d_nbe[k + 5], n6 = d_nbe[k + 6], n7 = d_nbe[k + 7];
        if (act) {
            float4 r0 = base[(size_t)n0 * 75 + lane];
            float4 r1 = base[(size_t)n1 * 75 + lane];
            float4 r2 = base[(size_t)n2 * 75 + lane];
            float4 r3 = base[(size_t)n3 * 75 + lane];
            float4 r4 = base[(size_t)n4 * 75 + lane];
            float4 r5 = base[(size_t)n5 * 75 + lane];
            float4 r6 = base[(size_t)n6 * 75 + lane];
            float4 r7 = base[(size_t)n7 * 75 + lane];
            acc = f4add(acc, f4add(f4add(r0, r1), f4add(r2, r3)));
            acc = f4add(acc, f4add(f4add(r4, r5), f4add(r6, r7)));
        }
    }
    for (; k < end; k++) {
        int n = d_nbe[k];
        if (act) acc = f4add(acc, base[(size_t)n * 75 + lane]);
    }
    if (act) {
        float b = d_Binv[e];
        float4 o = make_float4(acc.x * b, acc.y * b, acc.z * b, acc.w * b);
        ((float4*)d_ebuf)[(size_t)e * 75 + lane] = o;
    }
}

// ---------------- node -> edge, F=256 (layers 2,3; src = d_hbuf) ----------------
// 64-thread group per edge, 4 edges per block.
__global__ __launch_bounds__(256) void agg_n2e_256() {
    int grp = threadIdx.x >> 6;
    int lane = threadIdx.x & 63;
    int e = blockIdx.x * 4 + grp;
    int start = d_off_e[e], end = d_off_e[e + 1];
    const float4* base = (const float4*)d_hbuf;   // row stride 64 float4
    float4 acc = make_float4(0.f, 0.f, 0.f, 0.f);
    int k = start;
    for (; k + 8 <= end; k += 8) {
        int n0 = d_nbe[k],     n1 = d_nbe[k + 1], n2 = d_nbe[k + 2], n3 = d_nbe[k + 3];
        int n4 = d_nbe[k + 4], n5 = d_nbe[k + 5], n6 = d_nbe[k + 6], n7 = d_nbe[k + 7];
        float4 r0 = base[(size_t)n0 * 64 + lane];
        float4 r1 = base[(size_t)n1 * 64 + lane];
        float4 r2 = base[(size_t)n2 * 64 + lane];
        float4 r3 = base[(size_t)n3 * 64 + lane];
        float4 r4 = base[(size_t)n4 * 64 + lane];
        float4 r5 = base[(size_t)n5 * 64 + lane];
        float4 r6 = base[(size_t)n6 * 64 + lane];
        float4 r7 = base[(size_t)n7 * 64 + lane];
        acc = f4add(acc, f4add(f4add(r0, r1), f4add(r2, r3)));
        acc = f4add(acc, f4add(f4add(r4, r5), f4add(r6, r7)));
    }
    for (; k < end; k++) {
        int n = d_nbe[k];
        acc = f4add(acc, base[(size_t)n * 64 + lane]);
    }
    float b = d_Binv[e];
    float4 o = make_float4(acc.x * b, acc.y * b, acc.z * b, acc.w * b);
    ((float4*)d_ebuf)[(size_t)e * 64 + lane] = o;
}

// ---------------- edge -> node, F=256, lrelu (layers 1,2) ----------------
// 64-thread group per node, 4 nodes per block.
__global__ __launch_bounds__(256) void agg_e2n_256(const float* __restrict__ bias) {
    int grp = threadIdx.x >> 6;
    int lane = threadIdx.x & 63;
    int n = blockIdx.x * 4 + grp;
    int start = d_off_n[n], end = d_off_n[n + 1];
    const float4* base = (const float4*)d_gbuf;   // row stride 64 float4
    float4 acc = make_float4(0.f, 0.f, 0.f, 0.f);
    int k = start;
    for (; k + 4 <= end; k += 4) {
        int e0 = d_ebn[k], e1 = d_ebn[k + 1], e2 = d_ebn[k + 2], e3 = d_ebn[k + 3];
        float4 r0 = base[(size_t)e0 * 64 + lane];
        float4 r1 = base[(size_t)e1 * 64 + lane];
        float4 r2 = base[(size_t)e2 * 64 + lane];
        float4 r3 = base[(size_t)e3 * 64 + lane];
        acc = f4add(acc, f4add(f4add(r0, r1), f4add(r2, r3)));
    }
    for (; k < end; k++) {
        int e = d_ebn[k];
        acc = f4add(acc, base[(size_t)e * 64 + lane]);
    }
    float dv = d_Dinv[n];
    float4 bb = ((const float4*)bias)[lane];
    float4 v = make_float4(acc.x * dv + bb.x, acc.y * dv + bb.y,
                           acc.z * dv + bb.z, acc.w * dv + bb.w);
    v.x = (v.x > 0.f) ? v.x : 0.01f * v.x;
    v.y = (v.y > 0.f) ? v.y : 0.01f * v.y;
    v.z = (v.z > 0.f) ? v.z : 0.01f * v.z;
    v.w = (v.w > 0.f) ? v.w : 0.01f * v.w;
    ((float4*)d_hbuf)[(size_t)n * 64 + lane] = v;
}

// ---------------- edge -> node, F=128, no act, fused attn logits (layer 3) ----------------
// warp (32 lanes float4) per node, 8 nodes per block.
__global__ __launch_bounds__(256) void agg_e2n_128(const float* __restrict__ bias,
                                                   const float* __restrict__ attn_w,
                                                   const float* __restrict__ attn_b) {
    int w = threadIdx.x >> 5;
    int lane = threadIdx.x & 31;
    int n = blockIdx.x * 8 + w;
    int start = d_off_n[n], end = d_off_n[n + 1];
    const float4* base = (const float4*)d_gbuf;   // row stride 32 float4
    float4 acc = make_float4(0.f, 0.f, 0.f, 0.f);
    int k = start;
    for (; k + 4 <= end; k += 4) {
        int e0 = d_ebn[k], e1 = d_ebn[k + 1], e2 = d_ebn[k + 2], e3 = d_ebn[k + 3];
        float4 r0 = base[(size_t)e0 * 32 + lane];
        float4 r1 = base[(size_t)e1 * 32 + lane];
        float4 r2 = base[(size_t)e2 * 32 + lane];
        float4 r3 = base[(size_t)e3 * 32 + lane];
        acc = f4add(acc, f4add(f4add(r0, r1), f4add(r2, r3)));
    }
    for (; k < end; k++) {
        int e = d_ebn[k];
        acc = f4add(acc, base[(size_t)e * 32 + lane]);
    }
    float dv = d_Dinv[n];
    float4 bb = ((const float4*)bias)[lane];
    float4 v = make_float4(acc.x * dv + bb.x, acc.y * dv + bb.y,
                           acc.z * dv + bb.z, acc.w * dv + bb.w);
    ((float4*)d_hbuf)[(size_t)n * 32 + lane] = v;
    float4 aw = ((const float4*)attn_w)[lane];
    float t = v.x * aw.x + v.y * aw.y + v.z * aw.z + v.w * aw.w;
    #pragma unroll
    for (int o = 16; o > 0; o >>= 1) t += __shfl_down_sync(0xffffffffu, t, o);
    if (lane == 0) d_logits[n] = t + attn_b[0];
}

// ---------------- TF32 tensor-core GEMM: d_gbuf[M,N] = d_ebuf[M,K] @ B[K,N] ----------------
__device__ __forceinline__ unsigned f2tf32(float f) {
    unsigned r;
    asm("cvt.rna.tf32.f32 %0, %1;" : "=r"(r) : "f"(f));
    return r;
}

__device__ __forceinline__ void mma_tf32(float* c, const unsigned* a, const unsigned* b) {
    asm volatile(
        "mma.sync.aligned.m16n8k8.row.col.f32.tf32.tf32.f32 "
        "{%0,%1,%2,%3}, {%4,%5,%6,%7}, {%8,%9}, {%0,%1,%2,%3};"
        : "+f"(c[0]), "+f"(c[1]), "+f"(c[2]), "+f"(c[3])
        : "r"(a[0]), "r"(a[1]), "r"(a[2]), "r"(a[3]), "r"(b[0]), "r"(b[1]));
}

// Block tile 128x128, BK=32; 8 warps as 2(M) x 4(N); warp tile 64x32.
__global__ __launch_bounds__(256) void gemm_tf32(const float* __restrict__ Bg,
                                                 int M, int K, int N) {
    __shared__ unsigned As[32][132];   // [k][m]
    __shared__ unsigned Bs[32][132];   // [k][n]
    const float* A = d_ebuf;
    float* C = d_gbuf;

    int tid = threadIdx.x;
    int warp = tid >> 5, lane = tid & 31;
    int g = lane >> 2, tig = lane & 3;
    int wr = warp >> 2;        // 0..1
    int wc = warp & 3;         // 0..3
    int row0 = blockIdx.y * 128;
    int col0 = blockIdx.x * 128;

    float acc[4][4][4];
    #pragma unroll
    for (int mt = 0; mt < 4; mt++)
        #pragma unroll
        for (int nt = 0; nt < 4; nt++)
            #pragma unroll
            for (int i = 0; i < 4; i++) acc[mt][nt][i] = 0.0f;

    int nk = (K + 31) >> 5;
    for (int kt = 0; kt < nk; kt++) {
        int k0 = kt << 5;
        // load A tile -> As[k][m] (transposed, cvt to tf32)
        #pragma unroll
        for (int i = 0; i < 4; i++) {
            int v = tid + i * 256;
            int m = v >> 3, q = v & 7;
            int gm = row0 + m, gk = k0 + q * 4;
            float4 av;
            if (gm < M && gk + 3 < K) {
                av = *(const float4*)&A[(size_t)gm * K + gk];
            } else {
                av.x = (gm < M && gk + 0 < K) ? A[(size_t)gm * K + gk + 0] : 0.f;
                av.y = (gm < M && gk + 1 < K) ? A[(size_t)gm * K + gk + 1] : 0.f;
                av.z = (gm < M && gk + 2 < K) ? A[(size_t)gm * K + gk + 2] : 0.f;
                av.w = (gm < M && gk + 3 < K) ? A[(size_t)gm * K + gk + 3] : 0.f;
            }
            As[q * 4 + 0][m] = f2tf32(av.x);
            As[q * 4 + 1][m] = f2tf32(av.y);
            As[q * 4 + 2][m] = f2tf32(av.z);
            As[q * 4 + 3][m] = f2tf32(av.w);
        }
        // load B tile -> Bs[k][n]
        #pragma unroll
        for (int i = 0; i < 4; i++) {
            int v = tid + i * 256;
            int k = v >> 5, nq = v & 31;
            int gk = k0 + k, gn = col0 + nq * 4;
            float4 bv = make_float4(0.f, 0.f, 0.f, 0.f);
            if (gk < K) bv = *(const float4*)&Bg[(size_t)gk * N + gn];
            uint4 u;
            u.x = f2tf32(bv.x); u.y = f2tf32(bv.y);
            u.z = f2tf32(bv.z); u.w = f2tf32(bv.w);
            *(uint4*)&Bs[k][nq * 4] = u;
        }
        __syncthreads();

        #pragma unroll
        for (int ks = 0; ks < 4; ks++) {
            unsigned afr[4][4], bfr[4][2];
            #pragma unroll
            for (int mt = 0; mt < 4; mt++) {
                int m0 = wr * 64 + mt * 16;
                afr[mt][0] = As[ks * 8 + tig][m0 + g];
                afr[mt][1] = As[ks * 8 + tig][m0 + g + 8];
                afr[mt][2] = As[ks * 8 + tig + 4][m0 + g];
                afr[mt][3] = As[ks * 8 + tig + 4][m0 + g + 8];
            }
            #pragma unroll
            for (int nt = 0; nt < 4; nt++) {
                int n0 = wc * 32 + nt * 8;
                bfr[nt][0] = Bs[ks * 8 + tig][n0 + g];
                bfr[nt][1] = Bs[ks * 8 + tig + 4][n0 + g];
            }
            #pragma unroll
            for (int mt = 0; mt < 4; mt++)
                #pragma unroll
                for (int nt = 0; nt < 4; nt++)
                    mma_tf32(acc[mt][nt], afr[mt], bfr[nt]);
        }
        __syncthreads();
    }

    // epilogue
    #pragma unroll
    for (int mt = 0; mt < 4; mt++) {
        int ra = row0 + wr * 64 + mt * 16 + g;
        int rb = ra + 8;
        #pragma unroll
        for (int nt = 0; nt < 4; nt++) {
            int col = col0 + wc * 32 + nt * 8 + tig * 2;
            if (ra < M) *(float2*)&C[(size_t)ra * N + col] =
                make_float2(acc[mt][nt][0], acc[mt][nt][1]);
            if (rb < M) *(float2*)&C[(size_t)rb * N + col] =
                make_float2(acc[mt][nt][2], acc[mt][nt][3]);
        }
    }
}

// ---------------- attention pooling ----------------
__global__ void max1_kernel() {
    float m = -3.4e38f;
    int stride = gridDim.x * blockDim.x;
    for (int i = blockIdx.x * blockDim.x + threadIdx.x; i < N_NODES; i += stride)
        m = fmaxf(m, d_logits[i]);
    #pragma unroll
    for (int o = 16; o > 0; o >>= 1) m = fmaxf(m, __shfl_down_sync(0xffffffffu, m, o));
    __shared__ float ws[8];
    int lane = threadIdx.x & 31, warp = threadIdx.x >> 5;
    if (lane == 0) ws[warp] = m;
    __syncthreads();
    if (threadIdx.x == 0) {
        float mm = ws[0];
        for (int w = 1; w < (int)(blockDim.x >> 5); w++) mm = fmaxf(mm, ws[w]);
        d_pmax[blockIdx.x] = mm;
    }
}

__global__ void max2_kernel() {
    float m = d_pmax[threadIdx.x];
    #pragma unroll
    for (int o = 16; o > 0; o >>= 1) m = fmaxf(m, __shfl_down_sync(0xffffffffu, m, o));
    __shared__ float ws[8];
    int lane = threadIdx.x & 31, warp = threadIdx.x >> 5;
    if (lane == 0) ws[warp] = m;
    __syncthreads();
    if (threadIdx.x == 0) {
        float mm = ws[0];
        for (int w = 1; w < 8; w++) mm = fmaxf(mm, ws[w]);
        d_acc[131] = mm;
    }
}

__global__ void pool_kernel() {
    int f = threadIdx.x;      // 128 threads
    int lane = f & 31;
    float gm = d_acc[131];
    float accf = 0.0f, accse = 0.0f;
    for (int n = blockIdx.x; n < N_NODES; n += gridDim.x) {
        float w;
        if (lane == 0) w = __expf(d_logits[n] - gm);
        w = __shfl_sync(0xffffffffu, w, 0);
        accf += w * d_hbuf[(size_t)n * 128 + f];
        if (f == 0) accse += w;
    }
    atomicAdd(&d_acc[1 + f], accf);
    if (f == 0) atomicAdd(&d_acc[0], accse);
}

__global__ void final_kernel(float* __restrict__ out) {
    int f = threadIdx.x;
    if (f < 128) out[f] = d_acc[1 + f] / d_acc[0];
}

// ---------------- launch ----------------
extern "C" void kernel_launch(void* const* d_in, const int* in_sizes, int n_in,
                              void* d_out, int out_size) {
    const float* x      = (const float*)d_in[0];
    const int*   hei    = (const int*)d_in[1];
    const float* W1     = (const float*)d_in[2];
    const float* b1     = (const float*)d_in[3];
    const float* W2     = (const float*)d_in[4];
    const float* b2     = (const float*)d_in[5];
    const float* W3     = (const float*)d_in[6];
    const float* b3     = (const float*)d_in[7];
    const float* attn_w = (const float*)d_in[8];
    const float* attn_b = (const float*)d_in[9];
    const int* node_idx = hei;
    const int* edge_idx = hei + NNZ_CNT;
    float* out = (float*)d_out;

    const int NB_E = (N_EDGES + SCAN_CHUNK - 1) / SCAN_CHUNK;   // 5
    const int NB_N = (N_NODES + SCAN_CHUNK - 1) / SCAN_CHUNK;   // 25

    // CSR build
    zero_kernel<<<512, 256>>>();
    hist_kernel<<<(NNZ_CNT + 255) / 256, 256>>>(node_idx, edge_idx);
    partial_sum_e_kernel<<<NB_E, 256>>>();
    partial_sum_n_kernel<<<NB_N, 256>>>();
    scan_partials_e_kernel<<<1, 32>>>(NB_E);
    scan_partials_n_kernel<<<1, 32>>>(NB_N);
    local_scan_e_kernel<<<NB_E, 256>>>();
    local_scan_n_kernel<<<NB_N, 256>>>();
    inv_kernel<<<(N_NODES + 255) / 256, 256>>>();
    scatter_kernel<<<(NNZ_CNT + 255) / 256, 256>>>(node_idx, edge_idx);

    // layer 1
    agg_n2e_300<<<N_EDGES / 2, 256>>>(x);
    { dim3 g(2, (N_EDGES + 127) / 128); gemm_tf32<<<g, 256>>>(W1, N_EDGES, 300, 256); }
    agg_e2n_256<<<N_NODES / 4, 256>>>(b1);

    // layer 2
    agg_n2e_256<<<N_EDGES / 4, 256>>>();
    { dim3 g(2, (N_EDGES + 127) / 128); gemm_tf32<<<g, 256>>>(W2, N_EDGES, 256, 256); }
    agg_e2n_256<<<N_NODES / 4, 256>>>(b2);

    // layer 3 (fused attention logits)
    agg_n2e_256<<<N_EDGES / 4, 256>>>();
    { dim3 g(1, (N_EDGES + 127) / 128); gemm_tf32<<<g, 256>>>(W3, N_EDGES, 256, 128); }
    agg_e2n_128<<<N_NODES / 8, 256>>>(b3, attn_w, attn_b);

    // softmax-weighted pooling
    max1_kernel<<<256, 256>>>();
    max2_kernel<<<1, 256>>>();
    pool_kernel<<<1024, 128>>>();
    final_kernel<<<1, 128>>>(out);
}

// round 9
// speedup vs baseline: 2.4600x; 1.4486x over previous
#include <cuda_runtime.h>
#include <cuda_fp16.h>
#include <math.h>

#define N_NODES 100000
#define N_EDGES 20000
#define NNZ_CNT 1600000

// ---------------- static device scratch (no allocations allowed) ----------------
__device__ int   d_hist_e[N_EDGES];
__device__ int   d_hist_n[N_NODES];
__device__ int   d_off_e[N_EDGES + 1];
__device__ int   d_off_n[N_NODES + 1];
__device__ int   d_cur_e[N_EDGES];
__device__ int   d_cur_n[N_NODES];
__device__ int   d_nbe[NNZ_CNT];          // node ids grouped by edge
__device__ int   d_ebn[NNZ_CNT];          // edge ids grouped by node
__device__ float d_Binv[N_EDGES];
__device__ float d_Dinv[N_NODES];
__device__ int   d_bsum_e[8];
__device__ int   d_bsum_n[32];
// fp16 feature buffers (fp32 accumulate, fp16 store)
__device__ __align__(16) __half d_xh[(size_t)N_NODES * 320];    // x padded 300->320
__device__ __align__(16) __half d_ebuf[(size_t)N_EDGES * 320];  // edge agg (stride 320 L1, 256 L2/3)
__device__ __align__(16) __half d_gbuf[(size_t)N_EDGES * 256];  // edge GEMM out
__device__ __align__(16) __half d_hbuf[(size_t)N_NODES * 256];  // node features (L3 stores fp32 here, 128 wide)
__device__ float d_logits[N_NODES];
__device__ float d_pmax[256];
__device__ float d_acc[132];              // [0]=sumexp, [1..128]=sums, [131]=gmax

// ---------------- setup ----------------
__global__ void zero_kernel() {
    int stride = gridDim.x * blockDim.x;
    int i0 = blockIdx.x * blockDim.x + threadIdx.x;
    for (int i = i0; i < N_NODES; i += stride) { d_hist_n[i] = 0; d_cur_n[i] = 0; }
    for (int i = i0; i < N_EDGES; i += stride) { d_hist_e[i] = 0; d_cur_e[i] = 0; }
    if (i0 < 132) d_acc[i0] = 0.0f;
}

__global__ void hist_kernel(const int* __restrict__ ni, const int* __restrict__ ei) {
    int i = blockIdx.x * blockDim.x + threadIdx.x;
    if (i < NNZ_CNT) {
        atomicAdd(&d_hist_n[ni[i]], 1);
        atomicAdd(&d_hist_e[ei[i]], 1);
    }
}

// ---- multi-block exclusive scan ----
#define SCAN_CHUNK 4096   // 256 threads * 16 elements

__device__ __forceinline__ void partial_sum_dev(const int* __restrict__ hist,
                                                int* __restrict__ bsum, int n) {
    int t = threadIdx.x;
    int i0 = blockIdx.x * SCAN_CHUNK + t * 16;
    int s = 0;
    #pragma unroll
    for (int j = 0; j < 16; j++) { int i = i0 + j; s += (i < n) ? hist[i] : 0; }
    #pragma unroll
    for (int o = 16; o > 0; o >>= 1) s += __shfl_down_sync(0xffffffffu, s, o);
    __shared__ int ws[8];
    int lane = t & 31, w = t >> 5;
    if (lane == 0) ws[w] = s;
    __syncthreads();
    if (t == 0) {
        int tot = 0;
        #pragma unroll
        for (int k = 0; k < 8; k++) tot += ws[k];
        bsum[blockIdx.x] = tot;
    }
}

__device__ __forceinline__ void scan_partials_dev(int* __restrict__ bsum, int nb,
                                                  int* __restrict__ off, int n) {
    int t = threadIdx.x;  // 32 threads
    int v = (t < nb) ? bsum[t] : 0;
    int x = v;
    #pragma unroll
    for (int o = 1; o < 32; o <<= 1) {
        int y = __shfl_up_sync(0xffffffffu, x, o);
        if (t >= o) x += y;
    }
    if (t < nb) bsum[t] = x - v;
    if (t == 31) off[n] = x;
}

__device__ __forceinline__ void local_scan_dev(const int* __restrict__ hist,
                                               int* __restrict__ off,
                                               const int* __restrict__ bsum, int n) {
    int t = threadIdx.x;
    int i0 = blockIdx.x * SCAN_CHUNK + t * 16;
    int pre[16];
    int s = 0;
    #pragma unroll
    for (int j = 0; j < 16; j++) {
        int i = i0 + j;
        pre[j] = s;
        s += (i < n) ? hist[i] : 0;
    }
    int x = s;
    int lane = t & 31, w = t >> 5;
    #pragma unroll
    for (int o = 1; o < 32; o <<= 1) {
        int y = __shfl_up_sync(0xffffffffu, x, o);
        if (lane >= o) x += y;
    }
    __shared__ int ws[8];
    if (lane == 31) ws[w] = x;
    __syncthreads();
    int wbase = 0;
    #pragma unroll
    for (int k = 0; k < 8; k++) if (k < w) wbase += ws[k];
    int base = bsum[blockIdx.x] + wbase + (x - s);
    #pragma unroll
    for (int j = 0; j < 16; j++) {
        int i = i0 + j;
        if (i < n) off[i] = base + pre[j];
    }
}

__global__ void partial_sum_e_kernel() { partial_sum_dev(d_hist_e, d_bsum_e, N_EDGES); }
__global__ void partial_sum_n_kernel() { partial_sum_dev(d_hist_n, d_bsum_n, N_NODES); }
__global__ void scan_partials_e_kernel(int nb) { scan_partials_dev(d_bsum_e, nb, d_off_e, N_EDGES); }
__global__ void scan_partials_n_kernel(int nb) { scan_partials_dev(d_bsum_n, nb, d_off_n, N_NODES); }
__global__ void local_scan_e_kernel() { local_scan_dev(d_hist_e, d_off_e, d_bsum_e, N_EDGES); }
__global__ void local_scan_n_kernel() { local_scan_dev(d_hist_n, d_off_n, d_bsum_n, N_NODES); }

__global__ void inv_kernel() {
    int i = blockIdx.x * blockDim.x + threadIdx.x;
    if (i < N_NODES) { int d = d_hist_n[i]; d_Dinv[i] = d > 0 ? 1.0f / (float)d : 0.0f; }
    if (i < N_EDGES) { int d = d_hist_e[i]; d_Binv[i] = d > 0 ? 1.0f / (float)d : 0.0f; }
}

__global__ void scatter_kernel(const int* __restrict__ ni, const int* __restrict__ ei) {
    int i = blockIdx.x * blockDim.x + threadIdx.x;
    if (i >= NNZ_CNT) return;
    int n = ni[i], e = ei[i];
    int pe = atomicAdd(&d_cur_e[e], 1);
    d_nbe[d_off_e[e] + pe] = n;
    int pn = atomicAdd(&d_cur_n[n], 1);
    d_ebn[d_off_n[n] + pn] = e;
}

// ---------------- x -> fp16, pad 300 -> 320 ----------------
__global__ void conv_x_kernel(const float* __restrict__ x) {
    int i = blockIdx.x * blockDim.x + threadIdx.x;   // over N_NODES*160 half2
    if (i >= N_NODES * 160) return;
    int row = i / 160, c2 = i - row * 160;
    int col = c2 * 2;
    float a = (col < 300) ? x[(size_t)row * 300 + col] : 0.0f;
    float b = (col + 1 < 300) ? x[(size_t)row * 300 + col + 1] : 0.0f;
    ((__half2*)d_xh)[(size_t)row * 160 + c2] = __floats2half2_rn(a, b);
}

// ---------------- half helpers ----------------
__device__ __forceinline__ void acc8(float* a, uint4 v) {
    const __half2* h = (const __half2*)&v;
    float2 f0 = __half22float2(h[0]);
    float2 f1 = __half22float2(h[1]);
    float2 f2 = __half22float2(h[2]);
    float2 f3 = __half22float2(h[3]);
    a[0] += f0.x; a[1] += f0.y; a[2] += f1.x; a[3] += f1.y;
    a[4] += f2.x; a[5] += f2.y; a[6] += f3.x; a[7] += f3.y;
}

__device__ __forceinline__ uint4 pack8(const float* a) {
    uint4 v;
    __half2* h = (__half2*)&v;
    h[0] = __floats2half2_rn(a[0], a[1]);
    h[1] = __floats2half2_rn(a[2], a[3]);
    h[2] = __floats2half2_rn(a[4], a[5]);
    h[3] = __floats2half2_rn(a[6], a[7]);
    return v;
}

// ---------------- node -> edge, layer 1 (x_h, stride 320 halves = 40 uint4) ----------------
// 64-lane group per edge (40 active), 4 edges per block.
__global__ __launch_bounds__(256) void agg_n2e_320() {
    int grp = threadIdx.x >> 6;
    int lane = threadIdx.x & 63;
    int e = blockIdx.x * 4 + grp;
    bool act = lane < 40;
    int start = d_off_e[e], end = d_off_e[e + 1];
    const uint4* base = (const uint4*)d_xh;   // row stride 40
    float acc[8] = {0.f, 0.f, 0.f, 0.f, 0.f, 0.f, 0.f, 0.f};
    int k = start;
    for (; k + 8 <= end; k += 8) {
        int n0 = d_nbe[k],     n1 = d_nbe[k + 1], n2 = d_nbe[k + 2], n3 = d_nbe[k + 3];
        int n4 = d_nbe[k + 4], n5 = d_nbe[k + 5], n6 = d_nbe[k + 6], n7 = d_nbe[k + 7];
        if (act) {
            uint4 r0 = base[(size_t)n0 * 40 + lane];
            uint4 r1 = base[(size_t)n1 * 40 + lane];
            uint4 r2 = base[(size_t)n2 * 40 + lane];
            uint4 r3 = base[(size_t)n3 * 40 + lane];
            uint4 r4 = base[(size_t)n4 * 40 + lane];
            uint4 r5 = base[(size_t)n5 * 40 + lane];
            uint4 r6 = base[(size_t)n6 * 40 + lane];
            uint4 r7 = base[(size_t)n7 * 40 + lane];
            acc8(acc, r0); acc8(acc, r1); acc8(acc, r2); acc8(acc, r3);
            acc8(acc, r4); acc8(acc, r5); acc8(acc, r6); acc8(acc, r7);
        }
    }
    for (; k < end; k++) {
        int n = d_nbe[k];
        if (act) acc8(acc, base[(size_t)n * 40 + lane]);
    }
    if (act) {
        float b = d_Binv[e];
        #pragma unroll
        for (int j = 0; j < 8; j++) acc[j] *= b;
        ((uint4*)d_ebuf)[(size_t)e * 40 + lane] = pack8(acc);
    }
}

// ---------------- node -> edge, layers 2/3 (h, stride 256 halves = 32 uint4) ----------------
// warp per edge, 8 edges per block.
__global__ __launch_bounds__(256) void agg_n2e_256() {
    int w = threadIdx.x >> 5;
    int lane = threadIdx.x & 31;
    int e = blockIdx.x * 8 + w;
    int start = d_off_e[e], end = d_off_e[e + 1];
    const uint4* base = (const uint4*)d_hbuf;   // row stride 32
    float acc[8] = {0.f, 0.f, 0.f, 0.f, 0.f, 0.f, 0.f, 0.f};
    int k = start;
    for (; k + 8 <= end; k += 8) {
        int n0 = d_nbe[k],     n1 = d_nbe[k + 1], n2 = d_nbe[k + 2], n3 = d_nbe[k + 3];
        int n4 = d_nbe[k + 4], n5 = d_nbe[k + 5], n6 = d_nbe[k + 6], n7 = d_nbe[k + 7];
        uint4 r0 = base[(size_t)n0 * 32 + lane];
        uint4 r1 = base[(size_t)n1 * 32 + lane];
        uint4 r2 = base[(size_t)n2 * 32 + lane];
        uint4 r3 = base[(size_t)n3 * 32 + lane];
        uint4 r4 = base[(size_t)n4 * 32 + lane];
        uint4 r5 = base[(size_t)n5 * 32 + lane];
        uint4 r6 = base[(size_t)n6 * 32 + lane];
        uint4 r7 = base[(size_t)n7 * 32 + lane];
        acc8(acc, r0); acc8(acc, r1); acc8(acc, r2); acc8(acc, r3);
        acc8(acc, r4); acc8(acc, r5); acc8(acc, r6); acc8(acc, r7);
    }
    for (; k < end; k++) {
        int n = d_nbe[k];
        acc8(acc, base[(size_t)n * 32 + lane]);
    }
    float b = d_Binv[e];
    #pragma unroll
    for (int j = 0; j < 8; j++) acc[j] *= b;
    ((uint4*)d_ebuf)[(size_t)e * 32 + lane] = pack8(acc);
}

// ---------------- edge -> node, F=256, lrelu (layers 1,2) ----------------
// warp per node, 8 nodes per block.
__global__ __launch_bounds__(256) void agg_e2n_256(const float* __restrict__ bias) {
    int w = threadIdx.x >> 5;
    int lane = threadIdx.x & 31;
    int n = blockIdx.x * 8 + w;
    int start = d_off_n[n], end = d_off_n[n + 1];
    const uint4* base = (const uint4*)d_gbuf;   // row stride 32
    float acc[8] = {0.f, 0.f, 0.f, 0.f, 0.f, 0.f, 0.f, 0.f};
    int k = start;
    for (; k + 4 <= end; k += 4) {
        int e0 = d_ebn[k], e1 = d_ebn[k + 1], e2 = d_ebn[k + 2], e3 = d_ebn[k + 3];
        uint4 r0 = base[(size_t)e0 * 32 + lane];
        uint4 r1 = base[(size_t)e1 * 32 + lane];
        uint4 r2 = base[(size_t)e2 * 32 + lane];
        uint4 r3 = base[(size_t)e3 * 32 + lane];
        acc8(acc, r0); acc8(acc, r1); acc8(acc, r2); acc8(acc, r3);
    }
    for (; k < end; k++) {
        int e = d_ebn[k];
        acc8(acc, base[(size_t)e * 32 + lane]);
    }
    float dv = d_Dinv[n];
    float4 b0 = ((const float4*)bias)[lane * 2];
    float4 b1 = ((const float4*)bias)[lane * 2 + 1];
    float bb[8] = {b0.x, b0.y, b0.z, b0.w, b1.x, b1.y, b1.z, b1.w};
    #pragma unroll
    for (int j = 0; j < 8; j++) {
        float v = acc[j] * dv + bb[j];
        acc[j] = (v > 0.f) ? v : 0.01f * v;
    }
    ((uint4*)d_hbuf)[(size_t)n * 32 + lane] = pack8(acc);
}

// ---------------- edge -> node, F=128, no act, fused attn logits (layer 3) ----------------
// warp per node (uint2 = 4 halves per lane), 8 nodes per block; output fp32 into d_hbuf.
__global__ __launch_bounds__(256) void agg_e2n_128(const float* __restrict__ bias,
                                                   const float* __restrict__ attn_w,
                                                   const float* __restrict__ attn_b) {
    int w = threadIdx.x >> 5;
    int lane = threadIdx.x & 31;
    int n = blockIdx.x * 8 + w;
    int start = d_off_n[n], end = d_off_n[n + 1];
    const uint2* base = (const uint2*)d_gbuf;   // row = 128 halves = 32 uint2
    float a0 = 0.f, a1 = 0.f, a2 = 0.f, a3 = 0.f;
    int k = start;
    for (; k + 4 <= end; k += 4) {
        int e0 = d_ebn[k], e1 = d_ebn[k + 1], e2 = d_ebn[k + 2], e3 = d_ebn[k + 3];
        uint2 r0 = base[(size_t)e0 * 32 + lane];
        uint2 r1 = base[(size_t)e1 * 32 + lane];
        uint2 r2 = base[(size_t)e2 * 32 + lane];
        uint2 r3 = base[(size_t)e3 * 32 + lane];
        #pragma unroll
        for (int j = 0; j < 4; j++) {
            uint2 r = (j == 0) ? r0 : (j == 1) ? r1 : (j == 2) ? r2 : r3;
            float2 f0 = __half22float2(*(const __half2*)&r.x);
            float2 f1 = __half22float2(*(const __half2*)&r.y);
            a0 += f0.x; a1 += f0.y; a2 += f1.x; a3 += f1.y;
        }
    }
    for (; k < end; k++) {
        int e = d_ebn[k];
        uint2 r = base[(size_t)e * 32 + lane];
        float2 f0 = __half22float2(*(const __half2*)&r.x);
        float2 f1 = __half22float2(*(const __half2*)&r.y);
        a0 += f0.x; a1 += f0.y; a2 += f1.x; a3 += f1.y;
    }
    float dv = d_Dinv[n];
    float4 bb = ((const float4*)bias)[lane];
    float4 v = make_float4(a0 * dv + bb.x, a1 * dv + bb.y, a2 * dv + bb.z, a3 * dv + bb.w);
    ((float4*)d_hbuf)[(size_t)n * 32 + lane] = v;   // fp32 rows of 128
    float4 aw = ((const float4*)attn_w)[lane];
    float t = v.x * aw.x + v.y * aw.y + v.z * aw.z + v.w * aw.w;
    #pragma unroll
    for (int o = 16; o > 0; o >>= 1) t += __shfl_down_sync(0xffffffffu, t, o);
    if (lane == 0) d_logits[n] = t + attn_b[0];
}

// ---------------- TF32 tensor-core GEMM: gbuf[M,N](fp16) = ebuf[M,KA](fp16) @ B[K,N](fp32) ----------------
__device__ __forceinline__ unsigned f2tf32(float f) {
    unsigned r;
    asm("cvt.rna.tf32.f32 %0, %1;" : "=r"(r) : "f"(f));
    return r;
}

__device__ __forceinline__ void mma_tf32(float* c, const unsigned* a, const unsigned* b) {
    asm volatile(
        "mma.sync.aligned.m16n8k8.row.col.f32.tf32.tf32.f32 "
        "{%0,%1,%2,%3}, {%4,%5,%6,%7}, {%8,%9}, {%0,%1,%2,%3};"
        : "+f"(c[0]), "+f"(c[1]), "+f"(c[2]), "+f"(c[3])
        : "r"(a[0]), "r"(a[1]), "r"(a[2]), "r"(a[3]), "r"(b[0]), "r"(b[1]));
}

// Block tile 128x128, BK=32; 8 warps as 2(M) x 4(N); warp tile 64x32.
// strideA = padded K of ebuf in halves (multiple of 32, zero-padded past K).
__global__ __launch_bounds__(256) void gemm_tf32(const float* __restrict__ Bg,
                                                 int M, int K, int N, int strideA) {
    __shared__ unsigned As[32][132];   // [k][m]
    __shared__ unsigned Bs[32][132];   // [k][n]
    const __half* A = d_ebuf;
    __half* C = d_gbuf;

    int tid = threadIdx.x;
    int warp = tid >> 5, lane = tid & 31;
    int g = lane >> 2, tig = lane & 3;
    int wr = warp >> 2;
    int wc = warp & 3;
    int row0 = blockIdx.y * 128;
    int col0 = blockIdx.x * 128;

    float acc[4][4][4];
    #pragma unroll
    for (int mt = 0; mt < 4; mt++)
        #pragma unroll
        for (int nt = 0; nt < 4; nt++)
            #pragma unroll
            for (int i = 0; i < 4; i++) acc[mt][nt][i] = 0.0f;

    for (int k0 = 0; k0 < strideA; k0 += 32) {
        // load A tile (fp16 -> tf32, transposed): 128 rows x 32 k, 8 halves/thread
        #pragma unroll
        for (int i = 0; i < 2; i++) {
            int v = tid + i * 256;
            int m = v >> 2, q = v & 3;
            int gm = row0 + m, gk = k0 + q * 8;
            uint4 av = make_uint4(0u, 0u, 0u, 0u);
            if (gm < M) av = *(const uint4*)&A[(size_t)gm * strideA + gk];
            const __half2* hp = (const __half2*)&av;
            #pragma unroll
            for (int j = 0; j < 4; j++) {
                float2 f = __half22float2(hp[j]);
                As[q * 8 + 2 * j + 0][m] = f2tf32(f.x);
                As[q * 8 + 2 * j + 1][m] = f2tf32(f.y);
            }
        }
        // load B tile (fp32 -> tf32)
        #pragma unroll
        for (int i = 0; i < 4; i++) {
            int v = tid + i * 256;
            int kk = v >> 5, nq = v & 31;
            int gk = k0 + kk, gn = col0 + nq * 4;
            float4 bv = make_float4(0.f, 0.f, 0.f, 0.f);
            if (gk < K) bv = *(const float4*)&Bg[(size_t)gk * N + gn];
            uint4 u;
            u.x = f2tf32(bv.x); u.y = f2tf32(bv.y);
            u.z = f2tf32(bv.z); u.w = f2tf32(bv.w);
            *(uint4*)&Bs[kk][nq * 4] = u;
        }
        __syncthreads();

        #pragma unroll
        for (int ks = 0; ks < 4; ks++) {
            unsigned afr[4][4], bfr[4][2];
            #pragma unroll
            for (int mt = 0; mt < 4; mt++) {
                int m0 = wr * 64 + mt * 16;
                afr[mt][0] = As[ks * 8 + tig][m0 + g];
                afr[mt][1] = As[ks * 8 + tig][m0 + g + 8];
                afr[mt][2] = As[ks * 8 + tig + 4][m0 + g];
                afr[mt][3] = As[ks * 8 + tig + 4][m0 + g + 8];
            }
            #pragma unroll
            for (int nt = 0; nt < 4; nt++) {
                int n0 = wc * 32 + nt * 8;
                bfr[nt][0] = Bs[ks * 8 + tig][n0 + g];
                bfr[nt][1] = Bs[ks * 8 + tig + 4][n0 + g];
            }
            #pragma unroll
            for (int mt = 0; mt < 4; mt++)
                #pragma unroll
                for (int nt = 0; nt < 4; nt++)
                    mma_tf32(acc[mt][nt], afr[mt], bfr[nt]);
        }
        __syncthreads();
    }

    // epilogue: store fp16
    #pragma unroll
    for (int mt = 0; mt < 4; mt++) {
        int ra = row0 + wr * 64 + mt * 16 + g;
        int rb = ra + 8;
        #pragma unroll
        for (int nt = 0; nt < 4; nt++) {
            int col = col0 + wc * 32 + nt * 8 + tig * 2;
            if (ra < M) *(__half2*)&C[(size_t)ra * N + col] =
                __floats2half2_rn(acc[mt][nt][0], acc[mt][nt][1]);
            if (rb < M) *(__half2*)&C[(size_t)rb * N + col] =
                __floats2half2_rn(acc[mt][nt][2], acc[mt][nt][3]);
        }
    }
}

// ---------------- attention pooling ----------------
__global__ void max1_kernel() {
    float m = -3.4e38f;
    int stride = gridDim.x * blockDim.x;
    for (int i = blockIdx.x * blockDim.x + threadIdx.x; i < N_NODES; i += stride)
        m = fmaxf(m, d_logits[i]);
    #pragma unroll
    for (int o = 16; o > 0; o >>= 1) m = fmaxf(m, __shfl_down_sync(0xffffffffu, m, o));
    __shared__ float ws[8];
    int lane = threadIdx.x & 31, warp = threadIdx.x >> 5;
    if (lane == 0) ws[warp] = m;
    __syncthreads();
    if (threadIdx.x == 0) {
        float mm = ws[0];
        for (int w = 1; w < (int)(blockDim.x >> 5); w++) mm = fmaxf(mm, ws[w]);
        d_pmax[blockIdx.x] = mm;
    }
}

__global__ void max2_kernel() {
    float m = d_pmax[threadIdx.x];
    #pragma unroll
    for (int o = 16; o > 0; o >>= 1) m = fmaxf(m, __shfl_down_sync(0xffffffffu, m, o));
    __shared__ float ws[8];
    int lane = threadIdx.x & 31, warp = threadIdx.x >> 5;
    if (lane == 0) ws[warp] = m;
    __syncthreads();
    if (threadIdx.x == 0) {
        float mm = ws[0];
        for (int w = 1; w < 8; w++) mm = fmaxf(mm, ws[w]);
        d_acc[131] = mm;
    }
}

__global__ void pool_kernel() {
    int f = threadIdx.x;      // 128 threads
    int lane = f & 31;
    float gm = d_acc[131];
    const float* h = (const float*)d_hbuf;   // fp32 rows of 128 (layer-3 output)
    float accf = 0.0f, accse = 0.0f;
    for (int n = blockIdx.x; n < N_NODES; n += gridDim.x) {
        float w;
        if (lane == 0) w = __expf(d_logits[n] - gm);
        w = __shfl_sync(0xffffffffu, w, 0);
        accf += w * h[(size_t)n * 128 + f];
        if (f == 0) accse += w;
    }
    atomicAdd(&d_acc[1 + f], accf);
    if (f == 0) atomicAdd(&d_acc[0], accse);
}

__global__ void final_kernel(float* __restrict__ out) {
    int f = threadIdx.x;
    if (f < 128) out[f] = d_acc[1 + f] / d_acc[0];
}

// ---------------- launch ----------------
extern "C" void kernel_launch(void* const* d_in, const int* in_sizes, int n_in,
                              void* d_out, int out_size) {
    const float* x      = (const float*)d_in[0];
    const int*   hei    = (const int*)d_in[1];
    const float* W1     = (const float*)d_in[2];
    const float* b1     = (const float*)d_in[3];
    const float* W2     = (const float*)d_in[4];
    const float* b2     = (const float*)d_in[5];
    const float* W3     = (const float*)d_in[6];
    const float* b3     = (const float*)d_in[7];
    const float* attn_w = (const float*)d_in[8];
    const float* attn_b = (const float*)d_in[9];
    const int* node_idx = hei;
    const int* edge_idx = hei + NNZ_CNT;
    float* out = (float*)d_out;

    const int NB_E = (N_EDGES + SCAN_CHUNK - 1) / SCAN_CHUNK;   // 5
    const int NB_N = (N_NODES + SCAN_CHUNK - 1) / SCAN_CHUNK;   // 25

    // CSR build + x conversion
    zero_kernel<<<512, 256>>>();
    hist_kernel<<<(NNZ_CNT + 255) / 256, 256>>>(node_idx, edge_idx);
    conv_x_kernel<<<(N_NODES * 160 + 255) / 256, 256>>>(x);
    partial_sum_e_kernel<<<NB_E, 256>>>();
    partial_sum_n_kernel<<<NB_N, 256>>>();
    scan_partials_e_kernel<<<1, 32>>>(NB_E);
    scan_partials_n_kernel<<<1, 32>>>(NB_N);
    local_scan_e_kernel<<<NB_E, 256>>>();
    local_scan_n_kernel<<<NB_N, 256>>>();
    inv_kernel<<<(N_NODES + 255) / 256, 256>>>();
    scatter_kernel<<<(NNZ_CNT + 255) / 256, 256>>>(node_idx, edge_idx);

    // layer 1 (K=300, ebuf stride 320)
    agg_n2e_320<<<N_EDGES / 4, 256>>>();
    { dim3 g(2, (N_EDGES + 127) / 128); gemm_tf32<<<g, 256>>>(W1, N_EDGES, 300, 256, 320); }
    agg_e2n_256<<<N_NODES / 8, 256>>>(b1);

    // layer 2 (K=256, stride 256)
    agg_n2e_256<<<N_EDGES / 8, 256>>>();
    { dim3 g(2, (N_EDGES + 127) / 128); gemm_tf32<<<g, 256>>>(W2, N_EDGES, 256, 256, 256); }
    agg_e2n_256<<<N_NODES / 8, 256>>>(b2);

    // layer 3 (N=128; fused attention logits)
    agg_n2e_256<<<N_EDGES / 8, 256>>>();
    { dim3 g(1, (N_EDGES + 127) / 128); gemm_tf32<<<g, 256>>>(W3, N_EDGES, 256, 128, 256); }
    agg_e2n_128<<<N_NODES / 8, 256>>>(b3, attn_w, attn_b);

    // softmax-weighted pooling
    max1_kernel<<<256, 256>>>();
    max2_kernel<<<1, 256>>>();
    pool_kernel<<<1024, 128>>>();
    final_kernel<<<1, 128>>>(out);
}

// round 12
// speedup vs baseline: 2.6613x; 1.0818x over previous
#include <cuda_runtime.h>
#include <cuda_fp16.h>
#include <math.h>

#define N_NODES 100000
#define N_EDGES 20000
#define NNZ_CNT 1600000

// ---------------- static device scratch (no allocations allowed) ----------------
__device__ int   d_hist_e[N_EDGES];
__device__ int   d_hist_n[N_NODES];
__device__ int   d_off_e[N_EDGES + 1];
__device__ int   d_off_n[N_NODES + 1];
__device__ int   d_cur_e[N_EDGES];
__device__ int   d_cur_n[N_NODES];
__device__ int   d_nbe[NNZ_CNT];          // node ids grouped by edge
__device__ int   d_ebn[NNZ_CNT];          // edge ids grouped by node
__device__ float d_Binv[N_EDGES];
__device__ float d_Dinv[N_NODES];
__device__ int   d_bsum_e[8];
__device__ int   d_bsum_n[32];
// fp16 feature buffers (fp32 accumulate, fp16 store)
__device__ __align__(16) __half d_xh[(size_t)N_NODES * 320];    // x padded 300->320
__device__ __align__(16) __half d_ebuf[(size_t)N_EDGES * 320];  // edge agg
__device__ __align__(16) __half d_gbuf[(size_t)N_EDGES * 256];  // edge GEMM out
__device__ __align__(16) __half d_hbuf[(size_t)N_NODES * 256];  // node features (L3: fp32, 128 wide)
// fp16 weights, padded K
__device__ __align__(16) __half d_w1h[320 * 256];
__device__ __align__(16) __half d_w2h[256 * 256];
__device__ __align__(16) __half d_w3h[256 * 128];
__device__ float d_logits[N_NODES];
__device__ float d_pmax[256];
__device__ float d_acc[132];              // [0]=sumexp, [1..128]=sums, [131]=gmax

// ---------------- setup ----------------
__global__ void zero_kernel() {
    int stride = gridDim.x * blockDim.x;
    int i0 = blockIdx.x * blockDim.x + threadIdx.x;
    for (int i = i0; i < N_NODES; i += stride) { d_hist_n[i] = 0; d_cur_n[i] = 0; }
    for (int i = i0; i < N_EDGES; i += stride) { d_hist_e[i] = 0; d_cur_e[i] = 0; }
    if (i0 < 132) d_acc[i0] = 0.0f;
}

// vectorized histogram: 4 incidences per thread
__global__ void hist_kernel(const int* __restrict__ ni, const int* __restrict__ ei) {
    int i = blockIdx.x * blockDim.x + threadIdx.x;
    if (i >= NNZ_CNT / 4) return;
    int4 n4 = ((const int4*)ni)[i];
    int4 e4 = ((const int4*)ei)[i];
    atomicAdd(&d_hist_n[n4.x], 1); atomicAdd(&d_hist_n[n4.y], 1);
    atomicAdd(&d_hist_n[n4.z], 1); atomicAdd(&d_hist_n[n4.w], 1);
    atomicAdd(&d_hist_e[e4.x], 1); atomicAdd(&d_hist_e[e4.y], 1);
    atomicAdd(&d_hist_e[e4.z], 1); atomicAdd(&d_hist_e[e4.w], 1);
}

// ---- multi-block exclusive scan ----
#define SCAN_CHUNK 4096   // 256 threads * 16 elements

__device__ __forceinline__ void partial_sum_dev(const int* __restrict__ hist,
                                                int* __restrict__ bsum, int n) {
    int t = threadIdx.x;
    int i0 = blockIdx.x * SCAN_CHUNK + t * 16;
    int s = 0;
    #pragma unroll
    for (int j = 0; j < 16; j++) { int i = i0 + j; s += (i < n) ? hist[i] : 0; }
    #pragma unroll
    for (int o = 16; o > 0; o >>= 1) s += __shfl_down_sync(0xffffffffu, s, o);
    __shared__ int ws[8];
    int lane = t & 31, w = t >> 5;
    if (lane == 0) ws[w] = s;
    __syncthreads();
    if (t == 0) {
        int tot = 0;
        #pragma unroll
        for (int k = 0; k < 8; k++) tot += ws[k];
        bsum[blockIdx.x] = tot;
    }
}

__device__ __forceinline__ void scan_partials_dev(int* __restrict__ bsum, int nb,
                                                  int* __restrict__ off, int n) {
    int t = threadIdx.x;  // 32 threads
    int v = (t < nb) ? bsum[t] : 0;
    int x = v;
    #pragma unroll
    for (int o = 1; o < 32; o <<= 1) {
        int y = __shfl_up_sync(0xffffffffu, x, o);
        if (t >= o) x += y;
    }
    if (t < nb) bsum[t] = x - v;
    if (t == 31) off[n] = x;
}

__device__ __forceinline__ void local_scan_dev(const int* __restrict__ hist,
                                               int* __restrict__ off,
                                               const int* __restrict__ bsum, int n) {
    int t = threadIdx.x;
    int i0 = blockIdx.x * SCAN_CHUNK + t * 16;
    int pre[16];
    int s = 0;
    #pragma unroll
    for (int j = 0; j < 16; j++) {
        int i = i0 + j;
        pre[j] = s;
        s += (i < n) ? hist[i] : 0;
    }
    int x = s;
    int lane = t & 31, w = t >> 5;
    #pragma unroll
    for (int o = 1; o < 32; o <<= 1) {
        int y = __shfl_up_sync(0xffffffffu, x, o);
        if (lane >= o) x += y;
    }
    __shared__ int ws[8];
    if (lane == 31) ws[w] = x;
    __syncthreads();
    int wbase = 0;
    #pragma unroll
    for (int k = 0; k < 8; k++) if (k < w) wbase += ws[k];
    int base = bsum[blockIdx.x] + wbase + (x - s);
    #pragma unroll
    for (int j = 0; j < 16; j++) {
        int i = i0 + j;
        if (i < n) off[i] = base + pre[j];
    }
}

__global__ void partial_sum_e_kernel() { partial_sum_dev(d_hist_e, d_bsum_e, N_EDGES); }
__global__ void partial_sum_n_kernel() { partial_sum_dev(d_hist_n, d_bsum_n, N_NODES); }
__global__ void scan_partials_e_kernel(int nb) { scan_partials_dev(d_bsum_e, nb, d_off_e, N_EDGES); }
__global__ void scan_partials_n_kernel(int nb) { scan_partials_dev(d_bsum_n, nb, d_off_n, N_NODES); }
__global__ void local_scan_e_kernel() { local_scan_dev(d_hist_e, d_off_e, d_bsum_e, N_EDGES); }
__global__ void local_scan_n_kernel() { local_scan_dev(d_hist_n, d_off_n, d_bsum_n, N_NODES); }

__global__ void inv_kernel() {
    int i = blockIdx.x * blockDim.x + threadIdx.x;
    if (i < N_NODES) { int d = d_hist_n[i]; d_Dinv[i] = d > 0 ? 1.0f / (float)d : 0.0f; }
    if (i < N_EDGES) { int d = d_hist_e[i]; d_Binv[i] = d > 0 ? 1.0f / (float)d : 0.0f; }
}

__global__ void scatter_kernel(const int* __restrict__ ni, const int* __restrict__ ei) {
    int i = blockIdx.x * blockDim.x + threadIdx.x;
    if (i >= NNZ_CNT) return;
    int n = ni[i], e = ei[i];
    int pe = atomicAdd(&d_cur_e[e], 1);
    d_nbe[d_off_e[e] + pe] = n;
    int pn = atomicAdd(&d_cur_n[n], 1);
    d_ebn[d_off_n[n] + pn] = e;
}

// ---------------- x -> fp16, pad 300 -> 320 ----------------
__global__ void conv_x_kernel(const float* __restrict__ x) {
    int i = blockIdx.x * blockDim.x + threadIdx.x;   // over N_NODES*160 half2
    if (i >= N_NODES * 160) return;
    int row = i / 160, c2 = i - row * 160;
    int col = c2 * 2;
    float a = (col < 300) ? x[(size_t)row * 300 + col] : 0.0f;
    float b = (col + 1 < 300) ? x[(size_t)row * 300 + col + 1] : 0.0f;
    ((__half2*)d_xh)[(size_t)row * 160 + c2] = __floats2half2_rn(a, b);
}

// ---------------- weight conversions (fp32 [K][N] -> fp16 [Kpad][N], zero pad) --------
__global__ void conv_w1_kernel(const float* __restrict__ W) {
    int i = blockIdx.x * blockDim.x + threadIdx.x;   // 320*256
    if (i >= 320 * 256) return;
    int k = i >> 8;
    d_w1h[i] = (k < 300) ? __float2half_rn(W[i]) : __float2half_rn(0.0f);
}
__global__ void conv_w2_kernel(const float* __restrict__ W) {
    int i = blockIdx.x * blockDim.x + threadIdx.x;   // 256*256
    if (i >= 256 * 256) return;
    d_w2h[i] = __float2half_rn(W[i]);
}
__global__ void conv_w3_kernel(const float* __restrict__ W) {
    int i = blockIdx.x * blockDim.x + threadIdx.x;   // 256*128
    if (i >= 256 * 128) return;
    d_w3h[i] = __float2half_rn(W[i]);
}

// ---------------- half helpers ----------------
__device__ __forceinline__ void acc8(float* a, uint4 v) {
    const __half2* h = (const __half2*)&v;
    float2 f0 = __half22float2(h[0]);
    float2 f1 = __half22float2(h[1]);
    float2 f2 = __half22float2(h[2]);
    float2 f3 = __half22float2(h[3]);
    a[0] += f0.x; a[1] += f0.y; a[2] += f1.x; a[3] += f1.y;
    a[4] += f2.x; a[5] += f2.y; a[6] += f3.x; a[7] += f3.y;
}

__device__ __forceinline__ uint4 pack8(const float* a) {
    uint4 v;
    __half2* h = (__half2*)&v;
    h[0] = __floats2half2_rn(a[0], a[1]);
    h[1] = __floats2half2_rn(a[2], a[3]);
    h[2] = __floats2half2_rn(a[4], a[5]);
    h[3] = __floats2half2_rn(a[6], a[7]);
    return v;
}

// ---------------- node -> edge, layer 1 (x_h, stride 320 halves = 40 uint4) ----------------
// 64-lane group per edge (40 active), 4 edges per block.
__global__ __launch_bounds__(256) void agg_n2e_320() {
    int grp = threadIdx.x >> 6;
    int lane = threadIdx.x & 63;
    int e = blockIdx.x * 4 + grp;
    bool act = lane < 40;
    int start = d_off_e[e], end = d_off_e[e + 1];
    const uint4* base = (const uint4*)d_xh;   // row stride 40
    float acc[8] = {0.f, 0.f, 0.f, 0.f, 0.f, 0.f, 0.f, 0.f};
    int k = start;
    for (; k + 8 <= end; k += 8) {
        int n0 = d_nbe[k],     n1 = d_nbe[k + 1], n2 = d_nbe[k + 2], n3 = d_nbe[k + 3];
        int n4 = d_nbe[k + 4], n5 = d_nbe[k + 5], n6 = d_nbe[k + 6], n7 = d_nbe[k + 7];
        if (act) {
            uint4 r0 = base[(size_t)n0 * 40 + lane];
            uint4 r1 = base[(size_t)n1 * 40 + lane];
            uint4 r2 = base[(size_t)n2 * 40 + lane];
            uint4 r3 = base[(size_t)n3 * 40 + lane];
            uint4 r4 = base[(size_t)n4 * 40 + lane];
            uint4 r5 = base[(size_t)n5 * 40 + lane];
            uint4 r6 = base[(size_t)n6 * 40 + lane];
            uint4 r7 = base[(size_t)n7 * 40 + lane];
            acc8(acc, r0); acc8(acc, r1); acc8(acc, r2); acc8(acc, r3);
            acc8(acc, r4); acc8(acc, r5); acc8(acc, r6); acc8(acc, r7);
        }
    }
    for (; k < end; k++) {
        int n = d_nbe[k];
        if (act) acc8(acc, base[(size_t)n * 40 + lane]);
    }
    if (act) {
        float b = d_Binv[e];
        #pragma unroll
        for (int j = 0; j < 8; j++) acc[j] *= b;
        ((uint4*)d_ebuf)[(size_t)e * 40 + lane] = pack8(acc);
    }
}

// ---------------- node -> edge, layers 2/3 (h, stride 256 halves = 32 uint4) ----------------
// warp per edge, 8 edges per block.
__global__ __launch_bounds__(256) void agg_n2e_256() {
    int w = threadIdx.x >> 5;
    int lane = threadIdx.x & 31;
    int e = blockIdx.x * 8 + w;
    int start = d_off_e[e], end = d_off_e[e + 1];
    const uint4* base = (const uint4*)d_hbuf;   // row stride 32
    float acc[8] = {0.f, 0.f, 0.f, 0.f, 0.f, 0.f, 0.f, 0.f};
    int k = start;
    for (; k + 8 <= end; k += 8) {
        int n0 = d_nbe[k],     n1 = d_nbe[k + 1], n2 = d_nbe[k + 2], n3 = d_nbe[k + 3];
        int n4 = d_nbe[k + 4], n5 = d_nbe[k + 5], n6 = d_nbe[k + 6], n7 = d_nbe[k + 7];
        uint4 r0 = base[(size_t)n0 * 32 + lane];
        uint4 r1 = base[(size_t)n1 * 32 + lane];
        uint4 r2 = base[(size_t)n2 * 32 + lane];
        uint4 r3 = base[(size_t)n3 * 32 + lane];
        uint4 r4 = base[(size_t)n4 * 32 + lane];
        uint4 r5 = base[(size_t)n5 * 32 + lane];
        uint4 r6 = base[(size_t)n6 * 32 + lane];
        uint4 r7 = base[(size_t)n7 * 32 + lane];
        acc8(acc, r0); acc8(acc, r1); acc8(acc, r2); acc8(acc, r3);
        acc8(acc, r4); acc8(acc, r5); acc8(acc, r6); acc8(acc, r7);
    }
    for (; k < end; k++) {
        int n = d_nbe[k];
        acc8(acc, base[(size_t)n * 32 + lane]);
    }
    float b = d_Binv[e];
    #pragma unroll
    for (int j = 0; j < 8; j++) acc[j] *= b;
    ((uint4*)d_ebuf)[(size_t)e * 32 + lane] = pack8(acc);
}

// ---------------- edge -> node, F=256, lrelu (layers 1,2) ----------------
// warp per node, 8 nodes per block, unroll 8.
__global__ __launch_bounds__(256) void agg_e2n_256(const float* __restrict__ bias) {
    int w = threadIdx.x >> 5;
    int lane = threadIdx.x & 31;
    int n = blockIdx.x * 8 + w;
    int start = d_off_n[n], end = d_off_n[n + 1];
    const uint4* base = (const uint4*)d_gbuf;   // row stride 32
    float acc[8] = {0.f, 0.f, 0.f, 0.f, 0.f, 0.f, 0.f, 0.f};
    int k = start;
    for (; k + 8 <= end; k += 8) {
        int e0 = d_ebn[k],     e1 = d_ebn[k + 1], e2 = d_ebn[k + 2], e3 = d_ebn[k + 3];
        int e4 = d_ebn[k + 4], e5 = d_ebn[k + 5], e6 = d_ebn[k + 6], e7 = d_ebn[k + 7];
        uint4 r0 = base[(size_t)e0 * 32 + lane];
        uint4 r1 = base[(size_t)e1 * 32 + lane];
        uint4 r2 = base[(size_t)e2 * 32 + lane];
        uint4 r3 = base[(size_t)e3 * 32 + lane];
        uint4 r4 = base[(size_t)e4 * 32 + lane];
        uint4 r5 = base[(size_t)e5 * 32 + lane];
        uint4 r6 = base[(size_t)e6 * 32 + lane];
        uint4 r7 = base[(size_t)e7 * 32 + lane];
        acc8(acc, r0); acc8(acc, r1); acc8(acc, r2); acc8(acc, r3);
        acc8(acc, r4); acc8(acc, r5); acc8(acc, r6); acc8(acc, r7);
    }
    for (; k < end; k++) {
        int e = d_ebn[k];
        acc8(acc, base[(size_t)e * 32 + lane]);
    }
    float dv = d_Dinv[n];
    float4 b0 = ((const float4*)bias)[lane * 2];
    float4 b1 = ((const float4*)bias)[lane * 2 + 1];
    float bb[8] = {b0.x, b0.y, b0.z, b0.w, b1.x, b1.y, b1.z, b1.w};
    #pragma unroll
    for (int j = 0; j < 8; j++) {
        float v = acc[j] * dv + bb[j];
        acc[j] = (v > 0.f) ? v : 0.01f * v;
    }
    ((uint4*)d_hbuf)[(size_t)n * 32 + lane] = pack8(acc);
}

// ---------------- edge -> node, F=128, no act, fused attn logits (layer 3) ----------------
__global__ __launch_bounds__(256) void agg_e2n_128(const float* __restrict__ bias,
                                                   const float* __restrict__ attn_w,
                                                   const float* __restrict__ attn_b) {
    int w = threadIdx.x >> 5;
    int lane = threadIdx.x & 31;
    int n = blockIdx.x * 8 + w;
    int start = d_off_n[n], end = d_off_n[n + 1];
    const uint2* base = (const uint2*)d_gbuf;   // row = 128 halves = 32 uint2
    float a0 = 0.f, a1 = 0.f, a2 = 0.f, a3 = 0.f;
    int k = start;
    for (; k + 4 <= end; k += 4) {
        int e0 = d_ebn[k], e1 = d_ebn[k + 1], e2 = d_ebn[k + 2], e3 = d_ebn[k + 3];
        uint2 r0 = base[(size_t)e0 * 32 + lane];
        uint2 r1 = base[(size_t)e1 * 32 + lane];
        uint2 r2 = base[(size_t)e2 * 32 + lane];
        uint2 r3 = base[(size_t)e3 * 32 + lane];
        #pragma unroll
        for (int j = 0; j < 4; j++) {
            uint2 r = (j == 0) ? r0 : (j == 1) ? r1 : (j == 2) ? r2 : r3;
            float2 f0 = __half22float2(*(const __half2*)&r.x);
            float2 f1 = __half22float2(*(const __half2*)&r.y);
            a0 += f0.x; a1 += f0.y; a2 += f1.x; a3 += f1.y;
        }
    }
    for (; k < end; k++) {
        int e = d_ebn[k];
        uint2 r = base[(size_t)e * 32 + lane];
        float2 f0 = __half22float2(*(const __half2*)&r.x);
        float2 f1 = __half22float2(*(const __half2*)&r.y);
        a0 += f0.x; a1 += f0.y; a2 += f1.x; a3 += f1.y;
    }
    float dv = d_Dinv[n];
    float4 bb = ((const float4*)bias)[lane];
    float4 v = make_float4(a0 * dv + bb.x, a1 * dv + bb.y, a2 * dv + bb.z, a3 * dv + bb.w);
    ((float4*)d_hbuf)[(size_t)n * 32 + lane] = v;   // fp32 rows of 128
    float4 aw = ((const float4*)attn_w)[lane];
    float t = v.x * aw.x + v.y * aw.y + v.z * aw.z + v.w * aw.w;
    #pragma unroll
    for (int o = 16; o > 0; o >>= 1) t += __shfl_down_sync(0xffffffffu, t, o);
    if (lane == 0) d_logits[n] = t + attn_b[0];
}

// ---------------- fp16 tensor-core GEMM: gbuf[M,N] = ebuf[M,Kpad] @ Wh[Kpad][N] ----------------
__device__ __forceinline__ void mma_f16(float* c, const unsigned* a, const unsigned* b) {
    asm volatile(
        "mma.sync.aligned.m16n8k16.row.col.f32.f16.f16.f32 "
        "{%0,%1,%2,%3}, {%4,%5,%6,%7}, {%8,%9}, {%0,%1,%2,%3};"
        : "+f"(c[0]), "+f"(c[1]), "+f"(c[2]), "+f"(c[3])
        : "r"(a[0]), "r"(a[1]), "r"(a[2]), "r"(a[3]), "r"(b[0]), "r"(b[1]));
}

// Block tile 128x128, BK=32; 8 warps as 2(M) x 4(N); warp tile 64x32.
// wsel: 0->d_w1h, 1->d_w2h, 2->d_w3h. Kpad = strideA (multiple of 32, weights zero-padded).
__global__ __launch_bounds__(256) void gemm_f16(int wsel, int M, int N, int strideA) {
    __shared__ __half As[128][40];        // [m][k], 32 used + 8 pad
    __shared__ __half Bs[32][136];        // [k][n], 128 used + 8 pad
    const __half* A = d_ebuf;
    const __half* Wh = (wsel == 0) ? d_w1h : (wsel == 1) ? d_w2h : d_w3h;
    __half* C = d_gbuf;

    int tid = threadIdx.x;
    int warp = tid >> 5, lane = tid & 31;
    int g = lane >> 2, tig = lane & 3;
    int wr = warp >> 2;        // 0..1
    int wc = warp & 3;         // 0..3
    int row0 = blockIdx.y * 128;
    int col0 = blockIdx.x * 128;

    float acc[4][4][4];
    #pragma unroll
    for (int mt = 0; mt < 4; mt++)
        #pragma unroll
        for (int nt = 0; nt < 4; nt++)
            #pragma unroll
            for (int i = 0; i < 4; i++) acc[mt][nt][i] = 0.0f;

    for (int k0 = 0; k0 < strideA; k0 += 32) {
        // A tile: 128 rows x 32 k halves; 2 uint4 per thread
        #pragma unroll
        for (int i = 0; i < 2; i++) {
            int v = tid + i * 256;
            int m = v >> 2, q = v & 3;
            int gm = row0 + m;
            uint4 av = make_uint4(0u, 0u, 0u, 0u);
            if (gm < M) av = *(const uint4*)&A[(size_t)gm * strideA + k0 + q * 8];
            *(uint4*)&As[m][q * 8] = av;
        }
        // B tile: 32 k-rows x 128 n halves; 2 uint4 per thread (k-major, coalesced)
        #pragma unroll
        for (int i = 0; i < 2; i++) {
            int v = tid + i * 256;
            int kk = v >> 4, nq = v & 15;
            uint4 bv = *(const uint4*)&Wh[(size_t)(k0 + kk) * N + col0 + nq * 8];
            *(uint4*)&Bs[kk][nq * 8] = bv;
        }
        __syncthreads();

        #pragma unroll
        for (int ks = 0; ks < 2; ks++) {
            unsigned afr[4][4], bfr[4][2];
            #pragma unroll
            for (int mt = 0; mt < 4; mt++) {
                int m0 = wr * 64 + mt * 16 + g;
                int kb = ks * 16 + tig * 2;
                afr[mt][0] = *(const unsigned*)&As[m0][kb];
                afr[mt][1] = *(const unsigned*)&As[m0 + 8][kb];
                afr[mt][2] = *(const unsigned*)&As[m0][kb + 8];
                afr[mt][3] = *(const unsigned*)&As[m0 + 8][kb + 8];
            }
            #pragma unroll
            for (int nt = 0; nt < 4; nt++) {
                int nn = wc * 32 + nt * 8 + g;
                int kb = ks * 16 + tig * 2;
                __half2 p0 = __halves2half2(Bs[kb][nn], Bs[kb + 1][nn]);
                __half2 p1 = __halves2half2(Bs[kb + 8][nn], Bs[kb + 9][nn]);
                bfr[nt][0] = *(const unsigned*)&p0;
                bfr[nt][1] = *(const unsigned*)&p1;
            }
            #pragma unroll
            for (int mt = 0; mt < 4; mt++)
                #pragma unroll
                for (int nt = 0; nt < 4; nt++)
                    mma_f16(acc[mt][nt], afr[mt], bfr[nt]);
        }
        __syncthreads();
    }

    // epilogue: fp32 acc -> fp16 store
    #pragma unroll
    for (int mt = 0; mt < 4; mt++) {
        int ra = row0 + wr * 64 + mt * 16 + g;
        int rb = ra + 8;
        #pragma unroll
        for (int nt = 0; nt < 4; nt++) {
            int col = col0 + wc * 32 + nt * 8 + tig * 2;
            if (ra < M) *(__half2*)&C[(size_t)ra * N + col] =
                __floats2half2_rn(acc[mt][nt][0], acc[mt][nt][1]);
            if (rb < M) *(__half2*)&C[(size_t)rb * N + col] =
                __floats2half2_rn(acc[mt][nt][2], acc[mt][nt][3]);
        }
    }
}

// ---------------- attention pooling ----------------
__global__ void max1_kernel() {
    float m = -3.4e38f;
    int stride = gridDim.x * blockDim.x;
    for (int i = blockIdx.x * blockDim.x + threadIdx.x; i < N_NODES; i += stride)
        m = fmaxf(m, d_logits[i]);
    #pragma unroll
    for (int o = 16; o > 0; o >>= 1) m = fmaxf(m, __shfl_down_sync(0xffffffffu, m, o));
    __shared__ float ws[8];
    int lane = threadIdx.x & 31, warp = threadIdx.x >> 5;
    if (lane == 0) ws[warp] = m;
    __syncthreads();
    if (threadIdx.x == 0) {
        float mm = ws[0];
        for (int w = 1; w < (int)(blockDim.x >> 5); w++) mm = fmaxf(mm, ws[w]);
        d_pmax[blockIdx.x] = mm;
    }
}

__global__ void max2_kernel() {
    float m = d_pmax[threadIdx.x];
    #pragma unroll
    for (int o = 16; o > 0; o >>= 1) m = fmaxf(m, __shfl_down_sync(0xffffffffu, m, o));
    __shared__ float ws[8];
    int lane = threadIdx.x & 31, warp = threadIdx.x >> 5;
    if (lane == 0) ws[warp] = m;
    __syncthreads();
    if (threadIdx.x == 0) {
        float mm = ws[0];
        for (int w = 1; w < 8; w++) mm = fmaxf(mm, ws[w]);
        d_acc[131] = mm;
    }
}

__global__ void pool_kernel() {
    int f = threadIdx.x;      // 128 threads
    int lane = f & 31;
    float gm = d_acc[131];
    const float* h = (const float*)d_hbuf;   // fp32 rows of 128 (layer-3 output)
    float accf = 0.0f, accse = 0.0f;
    for (int n = blockIdx.x; n < N_NODES; n += gridDim.x) {
        float w;
        if (lane == 0) w = __expf(d_logits[n] - gm);
        w = __shfl_sync(0xffffffffu, w, 0);
        accf += w * h[(size_t)n * 128 + f];
        if (f == 0) accse += w;
    }
    atomicAdd(&d_acc[1 + f], accf);
    if (f == 0) atomicAdd(&d_acc[0], accse);
}

__global__ void final_kernel(float* __restrict__ out) {
    int f = threadIdx.x;
    if (f < 128) out[f] = d_acc[1 + f] / d_acc[0];
}

// ---------------- launch ----------------
extern "C" void kernel_launch(void* const* d_in, const int* in_sizes, int n_in,
                              void* d_out, int out_size) {
    const float* x      = (const float*)d_in[0];
    const int*   hei    = (const int*)d_in[1];
    const float* W1     = (const float*)d_in[2];
    const float* b1     = (const float*)d_in[3];
    const float* W2     = (const float*)d_in[4];
    const float* b2     = (const float*)d_in[5];
    const float* W3     = (const float*)d_in[6];
    const float* b3     = (const float*)d_in[7];
    const float* attn_w = (const float*)d_in[8];
    const float* attn_b = (const float*)d_in[9];
    const int* node_idx = hei;
    const int* edge_idx = hei + NNZ_CNT;
    float* out = (float*)d_out;

    const int NB_E = (N_EDGES + SCAN_CHUNK - 1) / SCAN_CHUNK;   // 5
    const int NB_N = (N_NODES + SCAN_CHUNK - 1) / SCAN_CHUNK;   // 25

    // CSR build + conversions
    zero_kernel<<<512, 256>>>();
    hist_kernel<<<(NNZ_CNT / 4 + 255) / 256, 256>>>(node_idx, edge_idx);
    conv_x_kernel<<<(N_NODES * 160 + 255) / 256, 256>>>(x);
    conv_w1_kernel<<<(320 * 256 + 255) / 256, 256>>>(W1);
    conv_w2_kernel<<<(256 * 256 + 255) / 256, 256>>>(W2);
    conv_w3_kernel<<<(256 * 128 + 255) / 256, 256>>>(W3);
    partial_sum_e_kernel<<<NB_E, 256>>>();
    partial_sum_n_kernel<<<NB_N, 256>>>();
    scan_partials_e_kernel<<<1, 32>>>(NB_E);
    scan_partials_n_kernel<<<1, 32>>>(NB_N);
    local_scan_e_kernel<<<NB_E, 256>>>();
    local_scan_n_kernel<<<NB_N, 256>>>();
    inv_kernel<<<(N_NODES + 255) / 256, 256>>>();
    scatter_kernel<<<(NNZ_CNT + 255) / 256, 256>>>(node_idx, edge_idx);

    // layer 1 (Kpad=320)
    agg_n2e_320<<<N_EDGES / 4, 256>>>();
    { dim3 g(2, (N_EDGES + 127) / 128); gemm_f16<<<g, 256>>>(0, N_EDGES, 256, 320); }
    agg_e2n_256<<<N_NODES / 8, 256>>>(b1);

    // layer 2 (Kpad=256)
    agg_n2e_256<<<N_EDGES / 8, 256>>>();
    { dim3 g(2, (N_EDGES + 127) / 128); gemm_f16<<<g, 256>>>(1, N_EDGES, 256, 256); }
    agg_e2n_256<<<N_NODES / 8, 256>>>(b2);

    // layer 3 (N=128; fused attention logits)
    agg_n2e_256<<<N_EDGES / 8, 256>>>();
    { dim3 g(1, (N_EDGES + 127) / 128); gemm_f16<<<g, 256>>>(2, N_EDGES, 128, 256); }
    agg_e2n_128<<<N_NODES / 8, 256>>>(b3, attn_w, attn_b);

    // softmax-weighted pooling
    max1_kernel<<<256, 256>>>();
    max2_kernel<<<1, 256>>>();
    pool_kernel<<<1024, 128>>>();
    final_kernel<<<1, 128>>>(out);
}

// round 13
// speedup vs baseline: 2.8203x; 1.0597x over previous
#include <cuda_runtime.h>
#include <cuda_fp16.h>
#include <math.h>

#define N_NODES 100000
#define N_EDGES 20000
#define NNZ_CNT 1600000

// ---------------- static device scratch (no allocations allowed) ----------------
__device__ int   d_hist_e[N_EDGES];
__device__ int   d_hist_n[N_NODES];
__device__ int   d_off_e[N_EDGES + 1];
__device__ int   d_off_n[N_NODES + 1];
__device__ int   d_cur_e[N_EDGES];
__device__ int   d_cur_n[N_NODES];
__device__ int   d_nbe[NNZ_CNT];          // node ids grouped by edge
__device__ int   d_ebn[NNZ_CNT];          // edge ids grouped by node
__device__ float d_Binv[N_EDGES];
__device__ float d_Dinv[N_NODES];
__device__ int   d_bsum_e[8];
__device__ int   d_bsum_n[32];
// fp16 feature buffers (fp32 accumulate, fp16 store)
__device__ __align__(16) __half d_xh[(size_t)N_NODES * 320];    // x padded 300->320
__device__ __align__(16) __half d_ebuf[(size_t)N_EDGES * 320];  // edge agg
__device__ __align__(16) __half d_gbuf[(size_t)N_EDGES * 256];  // edge GEMM out
__device__ __align__(16) __half d_hbuf[(size_t)N_NODES * 256];  // node features (L3: fp32, 128 wide)
// fp16 weights, padded K
__device__ __align__(16) __half d_w1h[320 * 256];
__device__ __align__(16) __half d_w2h[256 * 256];
__device__ __align__(16) __half d_w3h[256 * 128];
__device__ float d_logits[N_NODES];
__device__ float d_pmax[256];
__device__ float d_acc[132];              // [0]=sumexp, [1..128]=sums, [131]=gmax

#define NB_E_C 5    // ceil(20000/4096)
#define NB_N_C 25   // ceil(100000/4096)
#define SCAN_CHUNK 4096

// ---------------- merged prep: zero counters + convert weights ----------------
__global__ void prep_kernel(const float* __restrict__ W1, const float* __restrict__ W2,
                            const float* __restrict__ W3) {
    int stride = gridDim.x * blockDim.x;
    int i0 = blockIdx.x * blockDim.x + threadIdx.x;
    for (int i = i0; i < N_NODES; i += stride) { d_hist_n[i] = 0; d_cur_n[i] = 0; }
    for (int i = i0; i < N_EDGES; i += stride) { d_hist_e[i] = 0; d_cur_e[i] = 0; }
    if (i0 < 132) d_acc[i0] = 0.0f;
    for (int i = i0; i < 320 * 256; i += stride) {
        int k = i >> 8;
        d_w1h[i] = (k < 300) ? __float2half_rn(W1[i]) : __float2half_rn(0.0f);
    }
    for (int i = i0; i < 256 * 256; i += stride) d_w2h[i] = __float2half_rn(W2[i]);
    for (int i = i0; i < 256 * 128; i += stride) d_w3h[i] = __float2half_rn(W3[i]);
}

// vectorized histogram: 4 incidences per thread
__global__ void hist_kernel(const int* __restrict__ ni, const int* __restrict__ ei) {
    int i = blockIdx.x * blockDim.x + threadIdx.x;
    if (i >= NNZ_CNT / 4) return;
    int4 n4 = ((const int4*)ni)[i];
    int4 e4 = ((const int4*)ei)[i];
    atomicAdd(&d_hist_n[n4.x], 1); atomicAdd(&d_hist_n[n4.y], 1);
    atomicAdd(&d_hist_n[n4.z], 1); atomicAdd(&d_hist_n[n4.w], 1);
    atomicAdd(&d_hist_e[e4.x], 1); atomicAdd(&d_hist_e[e4.y], 1);
    atomicAdd(&d_hist_e[e4.z], 1); atomicAdd(&d_hist_e[e4.w], 1);
}

// ---- multi-block exclusive scan (merged e/n kernels) ----
__device__ __forceinline__ void partial_sum_dev(const int* __restrict__ hist,
                                                int* __restrict__ bsum, int n, int bid) {
    int t = threadIdx.x;
    int i0 = bid * SCAN_CHUNK + t * 16;
    int s = 0;
    #pragma unroll
    for (int j = 0; j < 16; j++) { int i = i0 + j; s += (i < n) ? hist[i] : 0; }
    #pragma unroll
    for (int o = 16; o > 0; o >>= 1) s += __shfl_down_sync(0xffffffffu, s, o);
    __shared__ int ws[8];
    int lane = t & 31, w = t >> 5;
    if (lane == 0) ws[w] = s;
    __syncthreads();
    if (t == 0) {
        int tot = 0;
        #pragma unroll
        for (int k = 0; k < 8; k++) tot += ws[k];
        bsum[bid] = tot;
    }
}

__global__ void partial_sum_all() {
    if (blockIdx.x < NB_E_C) partial_sum_dev(d_hist_e, d_bsum_e, N_EDGES, blockIdx.x);
    else                     partial_sum_dev(d_hist_n, d_bsum_n, N_NODES, blockIdx.x - NB_E_C);
}

__device__ __forceinline__ void scan_partials_dev(int* __restrict__ bsum, int nb,
                                                  int* __restrict__ off, int n, int t) {
    int v = (t < nb) ? bsum[t] : 0;
    int x = v;
    #pragma unroll
    for (int o = 1; o < 32; o <<= 1) {
        int y = __shfl_up_sync(0xffffffffu, x, o);
        if (t >= o) x += y;
    }
    if (t < nb) bsum[t] = x - v;
    if (t == 31) off[n] = x;
}

__global__ void scan_partials_all() {    // 1 block, 64 threads: warp0=edges, warp1=nodes
    int t = threadIdx.x;
    if (t < 32) scan_partials_dev(d_bsum_e, NB_E_C, d_off_e, N_EDGES, t);
    else        scan_partials_dev(d_bsum_n, NB_N_C, d_off_n, N_NODES, t - 32);
}

// local scan + fused inverse-degree computation
__device__ __forceinline__ void local_scan_dev(const int* __restrict__ hist,
                                               int* __restrict__ off,
                                               const int* __restrict__ bsum,
                                               float* __restrict__ inv, int n, int bid) {
    int t = threadIdx.x;
    int i0 = bid * SCAN_CHUNK + t * 16;
    int pre[16];
    int s = 0;
    #pragma unroll
    for (int j = 0; j < 16; j++) {
        int i = i0 + j;
        pre[j] = s;
        s += (i < n) ? hist[i] : 0;
    }
    int x = s;
    int lane = t & 31, w = t >> 5;
    #pragma unroll
    for (int o = 1; o < 32; o <<= 1) {
        int y = __shfl_up_sync(0xffffffffu, x, o);
        if (lane >= o) x += y;
    }
    __shared__ int ws[8];
    if (lane == 31) ws[w] = x;
    __syncthreads();
    int wbase = 0;
    #pragma unroll
    for (int k = 0; k < 8; k++) if (k < w) wbase += ws[k];
    int base = bsum[bid] + wbase + (x - s);
    #pragma unroll
    for (int j = 0; j < 16; j++) {
        int i = i0 + j;
        if (i < n) {
            off[i] = base + pre[j];
            int d = hist[i];
            inv[i] = (d > 0) ? 1.0f / (float)d : 0.0f;
        }
    }
}

__global__ void local_scan_all() {
    if (blockIdx.x < NB_E_C) local_scan_dev(d_hist_e, d_off_e, d_bsum_e, d_Binv, N_EDGES, blockIdx.x);
    else                     local_scan_dev(d_hist_n, d_off_n, d_bsum_n, d_Dinv, N_NODES, blockIdx.x - NB_E_C);
}

// vectorized scatter: 4 incidences per thread
__global__ void scatter_kernel(const int* __restrict__ ni, const int* __restrict__ ei) {
    int i = blockIdx.x * blockDim.x + threadIdx.x;
    if (i >= NNZ_CNT / 4) return;
    int4 n4 = ((const int4*)ni)[i];
    int4 e4 = ((const int4*)ei)[i];
    #pragma unroll
    for (int j = 0; j < 4; j++) {
        int n = (j == 0) ? n4.x : (j == 1) ? n4.y : (j == 2) ? n4.z : n4.w;
        int e = (j == 0) ? e4.x : (j == 1) ? e4.y : (j == 2) ? e4.z : e4.w;
        int pe = atomicAdd(&d_cur_e[e], 1);
        d_nbe[d_off_e[e] + pe] = n;
        int pn = atomicAdd(&d_cur_n[n], 1);
        d_ebn[d_off_n[n] + pn] = e;
    }
}

// ---------------- x -> fp16, pad 300 -> 320 (vectorized: float4 read, 4-half write) ------
__global__ void conv_x_kernel(const float* __restrict__ x) {
    int i = blockIdx.x * blockDim.x + threadIdx.x;   // over N_NODES * 80
    if (i >= N_NODES * 80) return;
    int row = i / 80, q = i - row * 80;
    if (q < 75) {
        float4 v = ((const float4*)x)[(size_t)row * 75 + q];
        uint2 o;
        ((__half2*)&o)[0] = __floats2half2_rn(v.x, v.y);
        ((__half2*)&o)[1] = __floats2half2_rn(v.z, v.w);
        *(uint2*)&d_xh[(size_t)row * 320 + q * 4] = o;
    } else {
        *(uint2*)&d_xh[(size_t)row * 320 + 300 + (q - 75) * 4] = make_uint2(0u, 0u);
    }
}

// ---------------- half helpers ----------------
__device__ __forceinline__ void acc8(float* a, uint4 v) {
    const __half2* h = (const __half2*)&v;
    float2 f0 = __half22float2(h[0]);
    float2 f1 = __half22float2(h[1]);
    float2 f2 = __half22float2(h[2]);
    float2 f3 = __half22float2(h[3]);
    a[0] += f0.x; a[1] += f0.y; a[2] += f1.x; a[3] += f1.y;
    a[4] += f2.x; a[5] += f2.y; a[6] += f3.x; a[7] += f3.y;
}

__device__ __forceinline__ uint4 pack8(const float* a) {
    uint4 v;
    __half2* h = (__half2*)&v;
    h[0] = __floats2half2_rn(a[0], a[1]);
    h[1] = __floats2half2_rn(a[2], a[3]);
    h[2] = __floats2half2_rn(a[4], a[5]);
    h[3] = __floats2half2_rn(a[6], a[7]);
    return v;
}

// ---------------- node -> edge, layer 1 (x_h, stride 320 halves = 40 uint4) ----------------
// 64-lane group per edge (40 active), 4 edges per block.
__global__ __launch_bounds__(256) void agg_n2e_320() {
    int grp = threadIdx.x >> 6;
    int lane = threadIdx.x & 63;
    int e = blockIdx.x * 4 + grp;
    bool act = lane < 40;
    int start = d_off_e[e], end = d_off_e[e + 1];
    const uint4* base = (const uint4*)d_xh;   // row stride 40
    float acc[8] = {0.f, 0.f, 0.f, 0.f, 0.f, 0.f, 0.f, 0.f};
    int k = start;
    for (; k + 8 <= end; k += 8) {
        int n0 = d_nbe[k],     n1 = d_nbe[k + 1], n2 = d_nbe[k + 2], n3 = d_nbe[k + 3];
        int n4 = d_nbe[k + 4], n5 = d_nbe[k + 5], n6 = d_nbe[k + 6], n7 = d_nbe[k + 7];
        if (act) {
            uint4 r0 = base[(size_t)n0 * 40 + lane];
            uint4 r1 = base[(size_t)n1 * 40 + lane];
            uint4 r2 = base[(size_t)n2 * 40 + lane];
            uint4 r3 = base[(size_t)n3 * 40 + lane];
            uint4 r4 = base[(size_t)n4 * 40 + lane];
            uint4 r5 = base[(size_t)n5 * 40 + lane];
            uint4 r6 = base[(size_t)n6 * 40 + lane];
            uint4 r7 = base[(size_t)n7 * 40 + lane];
            acc8(acc, r0); acc8(acc, r1); acc8(acc, r2); acc8(acc, r3);
            acc8(acc, r4); acc8(acc, r5); acc8(acc, r6); acc8(acc, r7);
        }
    }
    for (; k < end; k++) {
        int n = d_nbe[k];
        if (act) acc8(acc, base[(size_t)n * 40 + lane]);
    }
    if (act) {
        float b = d_Binv[e];
        #pragma unroll
        for (int j = 0; j < 8; j++) acc[j] *= b;
        ((uint4*)d_ebuf)[(size_t)e * 40 + lane] = pack8(acc);
    }
}

// ---------------- node -> edge, layers 2/3 (h, stride 256 halves = 32 uint4) ----------------
// warp per edge, 8 edges per block, unroll 16 (edge degree ~80).
__global__ __launch_bounds__(256) void agg_n2e_256() {
    int w = threadIdx.x >> 5;
    int lane = threadIdx.x & 31;
    int e = blockIdx.x * 8 + w;
    int start = d_off_e[e], end = d_off_e[e + 1];
    const uint4* base = (const uint4*)d_hbuf;   // row stride 32
    float acc[8] = {0.f, 0.f, 0.f, 0.f, 0.f, 0.f, 0.f, 0.f};
    int k = start;
    for (; k + 16 <= end; k += 16) {
        int idx[16];
        #pragma unroll
        for (int j = 0; j < 16; j++) idx[j] = d_nbe[k + j];
        uint4 r[16];
        #pragma unroll
        for (int j = 0; j < 16; j++) r[j] = base[(size_t)idx[j] * 32 + lane];
        #pragma unroll
        for (int j = 0; j < 16; j++) acc8(acc, r[j]);
    }
    for (; k + 4 <= end; k += 4) {
        int i0 = d_nbe[k], i1 = d_nbe[k + 1], i2 = d_nbe[k + 2], i3 = d_nbe[k + 3];
        uint4 r0 = base[(size_t)i0 * 32 + lane];
        uint4 r1 = base[(size_t)i1 * 32 + lane];
        uint4 r2 = base[(size_t)i2 * 32 + lane];
        uint4 r3 = base[(size_t)i3 * 32 + lane];
        acc8(acc, r0); acc8(acc, r1); acc8(acc, r2); acc8(acc, r3);
    }
    for (; k < end; k++) {
        int n = d_nbe[k];
        acc8(acc, base[(size_t)n * 32 + lane]);
    }
    float b = d_Binv[e];
    #pragma unroll
    for (int j = 0; j < 8; j++) acc[j] *= b;
    ((uint4*)d_ebuf)[(size_t)e * 32 + lane] = pack8(acc);
}

// ---------------- edge -> node, F=256, lrelu (layers 1,2) ----------------
// warp per node, 8 nodes per block, unroll 8 (node degree ~16).
__global__ __launch_bounds__(256) void agg_e2n_256(const float* __restrict__ bias) {
    int w = threadIdx.x >> 5;
    int lane = threadIdx.x & 31;
    int n = blockIdx.x * 8 + w;
    int start = d_off_n[n], end = d_off_n[n + 1];
    const uint4* base = (const uint4*)d_gbuf;   // row stride 32
    float acc[8] = {0.f, 0.f, 0.f, 0.f, 0.f, 0.f, 0.f, 0.f};
    int k = start;
    for (; k + 8 <= end; k += 8) {
        int e0 = d_ebn[k],     e1 = d_ebn[k + 1], e2 = d_ebn[k + 2], e3 = d_ebn[k + 3];
        int e4 = d_ebn[k + 4], e5 = d_ebn[k + 5], e6 = d_ebn[k + 6], e7 = d_ebn[k + 7];
        uint4 r0 = base[(size_t)e0 * 32 + lane];
        uint4 r1 = base[(size_t)e1 * 32 + lane];
        uint4 r2 = base[(size_t)e2 * 32 + lane];
        uint4 r3 = base[(size_t)e3 * 32 + lane];
        uint4 r4 = base[(size_t)e4 * 32 + lane];
        uint4 r5 = base[(size_t)e5 * 32 + lane];
        uint4 r6 = base[(size_t)e6 * 32 + lane];
        uint4 r7 = base[(size_t)e7 * 32 + lane];
        acc8(acc, r0); acc8(acc, r1); acc8(acc, r2); acc8(acc, r3);
        acc8(acc, r4); acc8(acc, r5); acc8(acc, r6); acc8(acc, r7);
    }
    for (; k < end; k++) {
        int e = d_ebn[k];
        acc8(acc, base[(size_t)e * 32 + lane]);
    }
    float dv = d_Dinv[n];
    float4 b0 = ((const float4*)bias)[lane * 2];
    float4 b1 = ((const float4*)bias)[lane * 2 + 1];
    float bb[8] = {b0.x, b0.y, b0.z, b0.w, b1.x, b1.y, b1.z, b1.w};
    #pragma unroll
    for (int j = 0; j < 8; j++) {
        float v = acc[j] * dv + bb[j];
        acc[j] = (v > 0.f) ? v : 0.01f * v;
    }
    ((uint4*)d_hbuf)[(size_t)n * 32 + lane] = pack8(acc);
}

// ---------------- edge -> node, F=128, no act, fused attn logits (layer 3) ----------------
__global__ __launch_bounds__(256) void agg_e2n_128(const float* __restrict__ bias,
                                                   const float* __restrict__ attn_w,
                                                   const float* __restrict__ attn_b) {
    int w = threadIdx.x >> 5;
    int lane = threadIdx.x & 31;
    int n = blockIdx.x * 8 + w;
    int start = d_off_n[n], end = d_off_n[n + 1];
    const uint2* base = (const uint2*)d_gbuf;   // row = 128 halves = 32 uint2
    float a0 = 0.f, a1 = 0.f, a2 = 0.f, a3 = 0.f;
    int k = start;
    for (; k + 8 <= end; k += 8) {
        uint2 r[8];
        #pragma unroll
        for (int j = 0; j < 8; j++) r[j] = base[(size_t)d_ebn[k + j] * 32 + lane];
        #pragma unroll
        for (int j = 0; j < 8; j++) {
            float2 f0 = __half22float2(*(const __half2*)&r[j].x);
            float2 f1 = __half22float2(*(const __half2*)&r[j].y);
            a0 += f0.x; a1 += f0.y; a2 += f1.x; a3 += f1.y;
        }
    }
    for (; k < end; k++) {
        int e = d_ebn[k];
        uint2 r = base[(size_t)e * 32 + lane];
        float2 f0 = __half22float2(*(const __half2*)&r.x);
        float2 f1 = __half22float2(*(const __half2*)&r.y);
        a0 += f0.x; a1 += f0.y; a2 += f1.x; a3 += f1.y;
    }
    float dv = d_Dinv[n];
    float4 bb = ((const float4*)bias)[lane];
    float4 v = make_float4(a0 * dv + bb.x, a1 * dv + bb.y, a2 * dv + bb.z, a3 * dv + bb.w);
    ((float4*)d_hbuf)[(size_t)n * 32 + lane] = v;   // fp32 rows of 128
    float4 aw = ((const float4*)attn_w)[lane];
    float t = v.x * aw.x + v.y * aw.y + v.z * aw.z + v.w * aw.w;
    #pragma unroll
    for (int o = 16; o > 0; o >>= 1) t += __shfl_down_sync(0xffffffffu, t, o);
    if (lane == 0) d_logits[n] = t + attn_b[0];
}

// ---------------- fp16 tensor-core GEMM (cp.async 2-stage pipeline) ----------------
// gbuf[M,N] = ebuf[M,Kpad] @ Wh[Kpad][N]
__device__ __forceinline__ void mma_f16(float* c, const unsigned* a, const unsigned* b) {
    asm volatile(
        "mma.sync.aligned.m16n8k16.row.col.f32.f16.f16.f32 "
        "{%0,%1,%2,%3}, {%4,%5,%6,%7}, {%8,%9}, {%0,%1,%2,%3};"
        : "+f"(c[0]), "+f"(c[1]), "+f"(c[2]), "+f"(c[3])
        : "r"(a[0]), "r"(a[1]), "r"(a[2]), "r"(a[3]), "r"(b[0]), "r"(b[1]));
}

// Block tile 128x128, BK=32; 8 warps as 2(M) x 4(N); warp tile 64x32.
__global__ __launch_bounds__(256) void gemm_f16(int wsel, int M, int N, int strideA) {
    __shared__ __half As[2][128][40];     // [stage][m][k], 32 used + 8 pad
    __shared__ __half Bs[2][32][136];     // [stage][k][n], 128 used + 8 pad
    const __half* A = d_ebuf;
    const __half* Wh = (wsel == 0) ? d_w1h : (wsel == 1) ? d_w2h : d_w3h;
    __half* C = d_gbuf;

    int tid = threadIdx.x;
    int warp = tid >> 5, lane = tid & 31;
    int g = lane >> 2, tig = lane & 3;
    int wr = warp >> 2;        // 0..1
    int wc = warp & 3;         // 0..3
    int row0 = blockIdx.y * 128;
    int col0 = blockIdx.x * 128;

    // per-thread load coords
    int am0 = tid >> 2, aq0 = tid & 3;               // A chunk 0
    int am1 = (tid + 256) >> 2, aq1 = (tid + 256) & 3;
    int bk0 = tid >> 4, bn0 = tid & 15;              // B chunk 0
    int bk1 = (tid + 256) >> 4, bn1 = (tid + 256) & 15;

    float acc[4][4][4];
    #pragma unroll
    for (int mt = 0; mt < 4; mt++)
        #pragma unroll
        for (int nt = 0; nt < 4; nt++)
            #pragma unroll
            for (int i = 0; i < 4; i++) acc[mt][nt][i] = 0.0f;

    int nk = strideA >> 5;

    // stage loader
    #define LOAD_STAGE(S, K0) do {                                                      \
        int gm0 = row0 + am0, gm1 = row0 + am1;                                         \
        const __half* s0 = &A[(size_t)((gm0 < M) ? gm0 : 0) * strideA + (K0) + aq0 * 8];\
        const __half* s1 = &A[(size_t)((gm1 < M) ? gm1 : 0) * strideA + (K0) + aq1 * 8];\
        int z0 = (gm0 < M) ? 16 : 0, z1 = (gm1 < M) ? 16 : 0;                           \
        unsigned d0 = (unsigned)__cvta_generic_to_shared(&As[S][am0][aq0 * 8]);         \
        unsigned d1 = (unsigned)__cvta_generic_to_shared(&As[S][am1][aq1 * 8]);         \
        asm volatile("cp.async.cg.shared.global [%0], [%1], 16, %2;" :: "r"(d0), "l"(s0), "r"(z0)); \
        asm volatile("cp.async.cg.shared.global [%0], [%1], 16, %2;" :: "r"(d1), "l"(s1), "r"(z1)); \
        const __half* t0 = &Wh[(size_t)((K0) + bk0) * N + col0 + bn0 * 8];              \
        const __half* t1 = &Wh[(size_t)((K0) + bk1) * N + col0 + bn1 * 8];              \
        unsigned e0 = (unsigned)__cvta_generic_to_shared(&Bs[S][bk0][bn0 * 8]);         \
        unsigned e1 = (unsigned)__cvta_generic_to_shared(&Bs[S][bk1][bn1 * 8]);         \
        asm volatile("cp.async.cg.shared.global [%0], [%1], 16;" :: "r"(e0), "l"(t0));  \
        asm volatile("cp.async.cg.shared.global [%0], [%1], 16;" :: "r"(e1), "l"(t1));  \
        asm volatile("cp.async.commit_group;");                                         \
    } while (0)

    LOAD_STAGE(0, 0);

    for (int kt = 0; kt < nk; kt++) {
        if (kt + 1 < nk) {
            LOAD_STAGE((kt + 1) & 1, (kt + 1) << 5);
            asm volatile("cp.async.wait_group 1;");
        } else {
            asm volatile("cp.async.wait_group 0;");
        }
        __syncthreads();
        int s = kt & 1;

        #pragma unroll
        for (int ks = 0; ks < 2; ks++) {
            unsigned afr[4][4], bfr[4][2];
            #pragma unroll
            for (int mt = 0; mt < 4; mt++) {
                int m0 = wr * 64 + mt * 16 + g;
                int kb = ks * 16 + tig * 2;
                afr[mt][0] = *(const unsigned*)&As[s][m0][kb];
                afr[mt][1] = *(const unsigned*)&As[s][m0 + 8][kb];
                afr[mt][2] = *(const unsigned*)&As[s][m0][kb + 8];
                afr[mt][3] = *(const unsigned*)&As[s][m0 + 8][kb + 8];
            }
            #pragma unroll
            for (int nt = 0; nt < 4; nt++) {
                int nn = wc * 32 + nt * 8 + g;
                int kb = ks * 16 + tig * 2;
                __half2 p0 = __halves2half2(Bs[s][kb][nn], Bs[s][kb + 1][nn]);
                __half2 p1 = __halves2half2(Bs[s][kb + 8][nn], Bs[s][kb + 9][nn]);
                bfr[nt][0] = *(const unsigned*)&p0;
                bfr[nt][1] = *(const unsigned*)&p1;
            }
            #pragma unroll
            for (int mt = 0; mt < 4; mt++)
                #pragma unroll
                for (int nt = 0; nt < 4; nt++)
                    mma_f16(acc[mt][nt], afr[mt], bfr[nt]);
        }
        __syncthreads();
    }
    #undef LOAD_STAGE

    // epilogue: fp32 acc -> fp16 store
    #pragma unroll
    for (int mt = 0; mt < 4; mt++) {
        int ra = row0 + wr * 64 + mt * 16 + g;
        int rb = ra + 8;
        #pragma unroll
        for (int nt = 0; nt < 4; nt++) {
            int col = col0 + wc * 32 + nt * 8 + tig * 2;
            if (ra < M) *(__half2*)&C[(size_t)ra * N + col] =
                __floats2half2_rn(acc[mt][nt][0], acc[mt][nt][1]);
            if (rb < M) *(__half2*)&C[(size_t)rb * N + col] =
                __floats2half2_rn(acc[mt][nt][2], acc[mt][nt][3]);
        }
    }
}

// ---------------- attention pooling ----------------
__global__ void max1_kernel() {
    float m = -3.4e38f;
    int stride = gridDim.x * blockDim.x;
    for (int i = blockIdx.x * blockDim.x + threadIdx.x; i < N_NODES; i += stride)
        m = fmaxf(m, d_logits[i]);
    #pragma unroll
    for (int o = 16; o > 0; o >>= 1) m = fmaxf(m, __shfl_down_sync(0xffffffffu, m, o));
    __shared__ float ws[8];
    int lane = threadIdx.x & 31, warp = threadIdx.x >> 5;
    if (lane == 0) ws[warp] = m;
    __syncthreads();
    if (threadIdx.x == 0) {
        float mm = ws[0];
        for (int w = 1; w < (int)(blockDim.x >> 5); w++) mm = fmaxf(mm, ws[w]);
        d_pmax[blockIdx.x] = mm;
    }
}

__global__ void max2_kernel() {
    float m = d_pmax[threadIdx.x];
    #pragma unroll
    for (int o = 16; o > 0; o >>= 1) m = fmaxf(m, __shfl_down_sync(0xffffffffu, m, o));
    __shared__ float ws[8];
    int lane = threadIdx.x & 31, warp = threadIdx.x >> 5;
    if (lane == 0) ws[warp] = m;
    __syncthreads();
    if (threadIdx.x == 0) {
        float mm = ws[0];
        for (int w = 1; w < 8; w++) mm = fmaxf(mm, ws[w]);
        d_acc[131] = mm;
    }
}

__global__ void pool_kernel() {
    int f = threadIdx.x;      // 128 threads
    int lane = f & 31;
    float gm = d_acc[131];
    const float* h = (const float*)d_hbuf;   // fp32 rows of 128 (layer-3 output)
    float accf = 0.0f, accse = 0.0f;
    for (int n = blockIdx.x; n < N_NODES; n += gridDim.x) {
        float w;
        if (lane == 0) w = __expf(d_logits[n] - gm);
        w = __shfl_sync(0xffffffffu, w, 0);
        accf += w * h[(size_t)n * 128 + f];
        if (f == 0) accse += w;
    }
    atomicAdd(&d_acc[1 + f], accf);
    if (f == 0) atomicAdd(&d_acc[0], accse);
}

__global__ void final_kernel(float* __restrict__ out) {
    int f = threadIdx.x;
    if (f < 128) out[f] = d_acc[1 + f] / d_acc[0];
}

// ---------------- launch ----------------
extern "C" void kernel_launch(void* const* d_in, const int* in_sizes, int n_in,
                              void* d_out, int out_size) {
    const float* x      = (const float*)d_in[0];
    const int*   hei    = (const int*)d_in[1];
    const float* W1     = (const float*)d_in[2];
    const float* b1     = (const float*)d_in[3];
    const float* W2     = (const float*)d_in[4];
    const float* b2     = (const float*)d_in[5];
    const float* W3     = (const float*)d_in[6];
    const float* b3     = (const float*)d_in[7];
    const float* attn_w = (const float*)d_in[8];
    const float* attn_b = (const float*)d_in[9];
    const int* node_idx = hei;
    const int* edge_idx = hei + NNZ_CNT;
    float* out = (float*)d_out;

    // CSR build + conversions
    prep_kernel<<<512, 256>>>(W1, W2, W3);
    hist_kernel<<<(NNZ_CNT / 4 + 255) / 256, 256>>>(node_idx, edge_idx);
    conv_x_kernel<<<(N_NODES * 80 + 255) / 256, 256>>>(x);
    partial_sum_all<<<NB_E_C + NB_N_C, 256>>>();
    scan_partials_all<<<1, 64>>>();
    local_scan_all<<<NB_E_C + NB_N_C, 256>>>();
    scatter_kernel<<<(NNZ_CNT / 4 + 255) / 256, 256>>>(node_idx, edge_idx);

    // layer 1 (Kpad=320)
    agg_n2e_320<<<N_EDGES / 4, 256>>>();
    { dim3 g(2, (N_EDGES + 127) / 128); gemm_f16<<<g, 256>>>(0, N_EDGES, 256, 320); }
    agg_e2n_256<<<N_NODES / 8, 256>>>(b1);

    // layer 2 (Kpad=256)
    agg_n2e_256<<<N_EDGES / 8, 256>>>();
    { dim3 g(2, (N_EDGES + 127) / 128); gemm_f16<<<g, 256>>>(1, N_EDGES, 256, 256); }
    agg_e2n_256<<<N_NODES / 8, 256>>>(b2);

    // layer 3 (N=128; fused attention logits)
    agg_n2e_256<<<N_EDGES / 8, 256>>>();
    { dim3 g(1, (N_EDGES + 127) / 128); gemm_f16<<<g, 256>>>(2, N_EDGES, 128, 256); }
    agg_e2n_128<<<N_NODES / 8, 256>>>(b3, attn_w, attn_b);

    // softmax-weighted pooling
    max1_kernel<<<256, 256>>>();
    max2_kernel<<<1, 256>>>();
    pool_kernel<<<1024, 128>>>();
    final_kernel<<<1, 128>>>(out);
}